// round 1
// baseline (speedup 1.0000x reference)
#include <cuda_runtime.h>
#include <math.h>
#include <stdint.h>

#define BB  128
#define EMB 512
#define HH  1024
#define H3  3072
#define VV  8192
#define TT  100

// ---------------- device scratch (no allocations allowed) ----------------
__device__ float g_h[BB * HH];                 // hidden state [B,H]
__device__ float g_gh[BB * H3];                // h @ w_hh^T + b_hh
__device__ float g_logits[BB * VV];            // classifier logits
__device__ int   g_idx[BB];                    // argmax feedback
__device__ float g_eproj[(size_t)VV * H3];     // emb_table @ w_ih^T + b_ih  (96 MB)

// ---------------- init: h = x, out[:,0,:] = log_softmax(one-hot), idx = 0 ----
__global__ void k_init(const float* __restrict__ x, float* __restrict__ out)
{
    int i = blockIdx.x * blockDim.x + threadIdx.x;
    // log_softmax of one-hot at index 0: logsumexp = log(e^1 + (V-1))
    float L = logf(expf(1.0f) + (float)(VV - 1));
    if (i < BB * VV) {
        int b = i / VV, v = i % VV;
        out[(size_t)b * TT * VV + v] = (v == 0 ? 1.0f : 0.0f) - L;
    }
    if (i < BB * HH) g_h[i] = x[i];
    if (i < BB)      g_idx[i] = 0;
}

// ---------------- fp32 GEMM:  C[M,N] = A[M,K] * W[N,K]^T + bias[N] ----------
// Tiles: BM=BN=64, BK=16, 256 threads, 4x4 per-thread microtile.
// Requires M%64==0, N%64==0, K%16==0 (true for all call sites).
__global__ __launch_bounds__(256)
void k_gemm(const float* __restrict__ A, const float* __restrict__ W,
            const float* __restrict__ bias, float* __restrict__ C,
            int M, int N, int K)
{
    const int BM = 64, BN = 64, BK = 16;
    __shared__ float As[16][68];   // [k][m], padded
    __shared__ float Bs[16][68];   // [k][n], padded

    const int tid = threadIdx.x;
    const int m0 = blockIdx.y * BM;
    const int n0 = blockIdx.x * BN;
    const int tx = tid & 15;       // 16 col-groups * 4 cols
    const int ty = tid >> 4;       // 16 row-groups * 4 rows

    float acc[4][4];
#pragma unroll
    for (int i = 0; i < 4; i++)
#pragma unroll
        for (int j = 0; j < 4; j++) acc[i][j] = 0.0f;

    // per-thread gmem load coords: 1 float4 per matrix per K-tile
    const int lm = tid >> 2;       // 0..63
    const int lk = (tid & 3) * 4;  // 0,4,8,12

    for (int k0 = 0; k0 < K; k0 += BK) {
        float4 av = *(const float4*)(A + (size_t)(m0 + lm) * K + k0 + lk);
        float4 bv = *(const float4*)(W + (size_t)(n0 + lm) * K + k0 + lk);
        As[lk + 0][lm] = av.x; As[lk + 1][lm] = av.y;
        As[lk + 2][lm] = av.z; As[lk + 3][lm] = av.w;
        Bs[lk + 0][lm] = bv.x; Bs[lk + 1][lm] = bv.y;
        Bs[lk + 2][lm] = bv.z; Bs[lk + 3][lm] = bv.w;
        __syncthreads();

#pragma unroll
        for (int k = 0; k < BK; k++) {
            float4 a = *(const float4*)&As[k][ty * 4];
            float4 b = *(const float4*)&Bs[k][tx * 4];
            float ar[4] = {a.x, a.y, a.z, a.w};
            float br[4] = {b.x, b.y, b.z, b.w};
#pragma unroll
            for (int i = 0; i < 4; i++)
#pragma unroll
                for (int j = 0; j < 4; j++)
                    acc[i][j] = fmaf(ar[i], br[j], acc[i][j]);
        }
        __syncthreads();
    }

#pragma unroll
    for (int i = 0; i < 4; i++) {
        int m = m0 + ty * 4 + i;
        float4 o;
        o.x = acc[i][0] + bias[n0 + tx * 4 + 0];
        o.y = acc[i][1] + bias[n0 + tx * 4 + 1];
        o.z = acc[i][2] + bias[n0 + tx * 4 + 2];
        o.w = acc[i][3] + bias[n0 + tx * 4 + 3];
        *(float4*)(C + (size_t)m * N + n0 + tx * 4) = o;
    }
}

// ---------------- GRU gate fusion: h = (1-z)*n + z*h -------------------------
__global__ void k_gates()
{
    int g = blockIdx.x * blockDim.x + threadIdx.x;   // B*H threads
    int b = g >> 10;
    int i = g & (HH - 1);
    const float* gi = g_eproj + (size_t)g_idx[b] * H3;
    const float* gh = g_gh + (size_t)b * H3;
    float r = 1.0f / (1.0f + expf(-(gi[i]          + gh[i])));
    float z = 1.0f / (1.0f + expf(-(gi[HH + i]     + gh[HH + i])));
    float n = tanhf(gi[2 * HH + i] + r * gh[2 * HH + i]);
    g_h[g] = (1.0f - z) * n + z * g_h[g];
}

// ---------------- log-softmax + argmax (one block per batch row) -------------
__global__ __launch_bounds__(1024)
void k_softmax(float* __restrict__ out, int t)
{
    const int b = blockIdx.x;
    const int tid = threadIdx.x;
    const float* row = g_logits + (size_t)b * VV;
    float* orow = out + ((size_t)b * TT + t) * VV;

    __shared__ float s_v[1024];
    __shared__ int   s_i[1024];

    float x[8];
    float mx = -__int_as_float(0x7f800000);  // -inf
    int   ai = 0;
#pragma unroll
    for (int j = 0; j < 8; j++) {
        int idx = tid + j * 1024;
        x[j] = row[idx];
        if (x[j] > mx) { mx = x[j]; ai = idx; }
    }
    s_v[tid] = mx; s_i[tid] = ai;
    __syncthreads();
#pragma unroll
    for (int s = 512; s > 0; s >>= 1) {
        if (tid < s) {
            float v2 = s_v[tid + s]; int i2 = s_i[tid + s];
            if (v2 > s_v[tid] || (v2 == s_v[tid] && i2 < s_i[tid])) {
                s_v[tid] = v2; s_i[tid] = i2;
            }
        }
        __syncthreads();
    }
    float gmax = s_v[0];
    int   gidx = s_i[0];
    __syncthreads();

    float sum = 0.0f;
#pragma unroll
    for (int j = 0; j < 8; j++) sum += expf(x[j] - gmax);
    s_v[tid] = sum;
    __syncthreads();
#pragma unroll
    for (int s = 512; s > 0; s >>= 1) {
        if (tid < s) s_v[tid] += s_v[tid + s];
        __syncthreads();
    }
    float lse = gmax + logf(s_v[0]);

#pragma unroll
    for (int j = 0; j < 8; j++)
        orow[tid + j * 1024] = x[j] - lse;

    if (tid == 0) g_idx[b] = gidx;
}

// ---------------- launch ----------------------------------------------------
extern "C" void kernel_launch(void* const* d_in, const int* in_sizes, int n_in,
                              void* d_out, int out_size)
{
    const float* x     = (const float*)d_in[0];
    const float* emb   = (const float*)d_in[1];
    const float* w_ih  = (const float*)d_in[2];
    const float* w_hh  = (const float*)d_in[3];
    const float* b_ih  = (const float*)d_in[4];
    const float* b_hh  = (const float*)d_in[5];
    const float* cls_w = (const float*)d_in[6];
    const float* cls_b = (const float*)d_in[7];
    float* out = (float*)d_out;

    float* eproj;  cudaGetSymbolAddress((void**)&eproj,  g_eproj);
    float* hbuf;   cudaGetSymbolAddress((void**)&hbuf,   g_h);
    float* ghbuf;  cudaGetSymbolAddress((void**)&ghbuf,  g_gh);
    float* logits; cudaGetSymbolAddress((void**)&logits, g_logits);

    // init: h = x, out[:,0,:], idx = 0
    k_init<<<(BB * VV + 255) / 256, 256>>>(x, out);

    // E_proj = emb_table @ w_ih^T + b_ih   [V, 3H]  (off the serial chain)
    k_gemm<<<dim3(H3 / 64, VV / 64), 256>>>(emb, w_ih, b_ih, eproj, VV, H3, EMB);

    for (int t = 1; t < TT; t++) {
        // gh = h @ w_hh^T + b_hh    [B, 3H]
        k_gemm<<<dim3(H3 / 64, BB / 64), 256>>>(hbuf, w_hh, b_hh, ghbuf, BB, H3, HH);
        // h = GRU(E_proj[idx], gh, h)
        k_gates<<<(BB * HH) / 256, 256>>>();
        // logits = h @ cls_w^T + cls_b   [B, V]
        k_gemm<<<dim3(VV / 64, BB / 64), 256>>>(hbuf, cls_w, cls_b, logits, BB, VV, HH);
        // out[:,t,:] = log_softmax(logits); idx = argmax
        k_softmax<<<BB, 1024>>>(out, t);
    }
}

// round 3
// speedup vs baseline: 1.1323x; 1.1323x over previous
#include <cuda_runtime.h>
#include <math.h>
#include <stdint.h>

#define BB  128
#define EMB 512
#define HH  1024
#define H3  3072
#define VV  8192
#define TT  100

// Does this compilation stage have arch-specific (tcgen05) features?
#if defined(__CUDA_ARCH__) && (__CUDA_ARCH__ >= 1000) && \
    (defined(__CUDA_ARCH_FEAT_SM103_ALL) || defined(__CUDA_ARCH_FEAT_SM100_ALL) || \
     defined(__CUDA_ARCH_SPECIFIC__) || defined(__CUDA_ARCH_FAMILY_SPECIFIC__))
#define HAS_TCGEN05 1
#else
#define HAS_TCGEN05 0
#endif

// ======================= device scratch (no allocs allowed) ==================
__device__ float g_h[BB * HH];
__device__ float g_h_hi[BB * HH];
__device__ float g_h_lo[BB * HH];
__device__ float g_gh[BB * H3];
__device__ float g_logits[BB * VV];
__device__ int   g_idx[BB];
__device__ float g_eproj[(size_t)VV * H3];
__device__ float g_emb_hi[(size_t)VV * EMB];
__device__ float g_emb_lo[(size_t)VV * EMB];
__device__ float g_wih_hi[(size_t)H3 * EMB];
__device__ float g_wih_lo[(size_t)H3 * EMB];
__device__ float g_whh_hi[(size_t)H3 * HH];
__device__ float g_whh_lo[(size_t)H3 * HH];
__device__ float g_cls_hi[(size_t)VV * HH];
__device__ float g_cls_lo[(size_t)VV * HH];

// ======================= common helpers =====================================
__device__ __forceinline__ float tf32r(float a) {
    uint32_t u;
    asm("cvt.rna.tf32.f32 %0, %1;" : "=r"(u) : "f"(a));
    return __uint_as_float(u);
}

#define TILE_BYTES 16384
#define GEMM_SMEM  (1024 + 8 * TILE_BYTES)

#if HAS_TCGEN05
// ======================= tcgen05-only PTX helpers ============================
__device__ __forceinline__ uint32_t smem_u32(const void* p) {
    uint32_t a;
    asm("{ .reg .u64 t; cvta.to.shared.u64 t, %1; cvt.u32.u64 %0, t; }"
        : "=r"(a) : "l"(p));
    return a;
}
__device__ __forceinline__ uint32_t elect_one() {
    uint32_t pred;
    asm volatile("{\n\t.reg .pred p;\n\telect.sync _|p, 0xFFFFFFFF;\n\t"
                 "selp.b32 %0, 1, 0, p;\n\t}" : "=r"(pred));
    return pred;
}
#define SMEM_SWIZZLE_128B(o) ((o) ^ (((o) >> 3) & 0x70))

static constexpr uint64_t SMEM_DESC_BASE_SW128 =
    (uint64_t(2)  << 61) | (uint64_t(1) << 46) | (uint64_t(64) << 32) | (uint64_t(1) << 16);
#define MAKE_SMEM_DESC(a) (SMEM_DESC_BASE_SW128 | ((uint64_t)((a) >> 4) & 0x3FFF))

#define TCGEN05_ALLOC(addr, n) \
    asm volatile("tcgen05.alloc.cta_group::1.sync.aligned.shared::cta.b32 [%0], %1;" \
                 :: "r"((uint32_t)(addr)), "r"((uint32_t)(n)) : "memory")
#define TCGEN05_DEALLOC(t, n) \
    asm volatile("tcgen05.dealloc.cta_group::1.sync.aligned.b32 %0, %1;" :: "r"(t), "r"((uint32_t)(n)))
#define TCGEN05_RELINQ() \
    asm volatile("tcgen05.relinquish_alloc_permit.cta_group::1.sync.aligned;")
#define TCGEN05_COMMIT(mb) \
    asm volatile("tcgen05.commit.cta_group::1.mbarrier::arrive::one.shared::cluster.b64 [%0];" \
                 :: "r"((uint32_t)(mb)) : "memory")
#define TCGEN05_FENCE_AFTER()  asm volatile("tcgen05.fence::after_thread_sync;" ::: "memory")
#define TCGEN05_FENCE_BEFORE() asm volatile("tcgen05.fence::before_thread_sync;" ::: "memory")
#define TCGEN05_WAIT_LD()      asm volatile("tcgen05.wait::ld.sync.aligned;" ::: "memory")

#define MBARRIER_INIT(mb, cnt) \
    asm volatile("mbarrier.init.shared.b64 [%0], %1;" :: "r"((uint32_t)(mb)), "r"((uint32_t)(cnt)) : "memory")

#define MBARRIER_WAIT_PARITY(mb, par) do {                                         \
    uint32_t _m = (uint32_t)(mb); uint32_t _p = (uint32_t)(par); uint32_t _d;      \
    asm volatile("{\n\t.reg .pred p;\n\t"                                          \
        "mbarrier.try_wait.parity.acquire.cta.shared::cta.b64 p, [%1], %2;\n\t"    \
        "selp.b32 %0, 1, 0, p;\n\t}" : "=r"(_d) : "r"(_m), "r"(_p) : "memory");    \
    if (!_d) {                                                                     \
        asm volatile("{\n\t.reg .pred P1;\n\t"                                     \
            "WL_%=:\n\t"                                                           \
            "mbarrier.try_wait.parity.acquire.cta.shared::cta.b64 P1, [%0], %1, 0x989680;\n\t" \
            "@P1 bra.uni WD_%=;\n\t"                                               \
            "bra.uni WL_%=;\n\t"                                                   \
            "WD_%=:\n\t}" :: "r"(_m), "r"(_p) : "memory");                         \
    }                                                                              \
} while (0)

#define TCGEN05_LD_32X32B_X32(r, ta) \
    asm volatile( \
        "tcgen05.ld.sync.aligned.32x32b.x32.b32 " \
        "{%0, %1, %2, %3, %4, %5, %6, %7, " \
        " %8, %9, %10, %11, %12, %13, %14, %15, " \
        " %16, %17, %18, %19, %20, %21, %22, %23, " \
        " %24, %25, %26, %27, %28, %29, %30, %31}, [%32];" \
        : "=r"((r)[0]),  "=r"((r)[1]),  "=r"((r)[2]),  "=r"((r)[3]), \
          "=r"((r)[4]),  "=r"((r)[5]),  "=r"((r)[6]),  "=r"((r)[7]), \
          "=r"((r)[8]),  "=r"((r)[9]),  "=r"((r)[10]), "=r"((r)[11]), \
          "=r"((r)[12]), "=r"((r)[13]), "=r"((r)[14]), "=r"((r)[15]), \
          "=r"((r)[16]), "=r"((r)[17]), "=r"((r)[18]), "=r"((r)[19]), \
          "=r"((r)[20]), "=r"((r)[21]), "=r"((r)[22]), "=r"((r)[23]), \
          "=r"((r)[24]), "=r"((r)[25]), "=r"((r)[26]), "=r"((r)[27]), \
          "=r"((r)[28]), "=r"((r)[29]), "=r"((r)[30]), "=r"((r)[31]) \
        : "r"(ta))

__device__ __forceinline__ void mma_tf32_ss(uint32_t d, uint64_t da, uint64_t db,
                                            uint32_t idesc, uint32_t en) {
    asm volatile(
        "{\n\t.reg .pred p;\n\t"
        "setp.ne.u32 p, %5, 0;\n\t"
        "tcgen05.mma.cta_group::1.kind::tf32 [%0], %1, %2, %3, {%4, %4, %4, %4}, p;\n\t}"
        :: "r"(d), "l"(da), "l"(db), "r"(idesc), "r"(0u), "r"(en) : "memory");
}

// idesc: dtype=F32(1), atype=btype=TF32(2), N=128, M=128
static constexpr uint32_t IDESC_TF32 =
    (1u << 4) | (2u << 7) | (2u << 10) | ((128u / 8u) << 17) | ((128u / 16u) << 24);
#endif  // HAS_TCGEN05

// ======================= 3xTF32 GEMM (dual path) =============================
// C[M,N] = (Ahi+Alo)[M,K] @ (Bhi+Blo)[N,K]^T + bias[N]
// grid = (N/128, M/128), 256 threads, GEMM_SMEM dynamic smem (tcgen05 path).
__global__ __launch_bounds__(256, 1)
void k_gemm_tc(const float* __restrict__ Ahi, const float* __restrict__ Alo,
               const float* __restrict__ Bhi, const float* __restrict__ Blo,
               const float* __restrict__ bias, float* __restrict__ C,
               int N, int K)
{
#if HAS_TCGEN05
    extern __shared__ char dsm[];
    char* smem = (char*)(((uintptr_t)dsm + 1023) & ~(uintptr_t)1023);
    const uint32_t sb = smem_u32(smem);
    __shared__ uint32_t s_tmem;
    __shared__ uint64_t s_mbar[2];

    const int tid = threadIdx.x;
    const int wid = tid >> 5;
    const int lid = tid & 31;
    const int m0 = blockIdx.y * 128;
    const int n0 = blockIdx.x * 128;

    if (wid == 0) {
        TCGEN05_ALLOC(smem_u32(&s_tmem), 128);
        TCGEN05_RELINQ();
    }
    if (tid == 0) {
        MBARRIER_INIT(smem_u32(&s_mbar[0]), 1);
        MBARRIER_INIT(smem_u32(&s_mbar[1]), 1);
    }
    __syncthreads();
    const uint32_t tmem = s_tmem;
    const uint32_t mb0 = smem_u32(&s_mbar[0]);
    const uint32_t mb1 = smem_u32(&s_mbar[1]);
    const bool lead = (wid == 0) && elect_one();

    const float* gsrc[4];
    gsrc[0] = Ahi + (size_t)m0 * K;
    gsrc[1] = Alo + (size_t)m0 * K;
    gsrc[2] = Bhi + (size_t)n0 * K;
    gsrc[3] = Blo + (size_t)n0 * K;

    const int nk = K >> 5;
    int ph0 = 0, ph1 = 0;

    for (int kt = 0; kt < nk; kt++) {
        const int s = kt & 1;
        if (kt >= 2) {
            if (s == 0) { MBARRIER_WAIT_PARITY(mb0, ph0 & 1); ph0++; }
            else        { MBARRIER_WAIT_PARITY(mb1, ph1 & 1); ph1++; }
        }
        const int k0 = kt << 5;
#pragma unroll
        for (int b = 0; b < 4; b++) {
            char* dst = smem + (s * 4 + b) * TILE_BYTES;
#pragma unroll
            for (int i = 0; i < 4; i++) {
                int e = tid + i * 256;
                int row = e >> 3, c4 = e & 7;
                float4 v = *(const float4*)(gsrc[b] + (size_t)row * K + k0 + c4 * 4);
                uint32_t off = (uint32_t)(row * 128 + c4 * 16);
                *(float4*)(dst + SMEM_SWIZZLE_128B(off)) = v;
            }
        }
        asm volatile("fence.proxy.async.shared::cta;" ::: "memory");
        __syncthreads();
        if (lead) {
#pragma unroll
            for (int term = 0; term < 3; term++) {
                const int abuf = (term == 2) ? 1 : 0;
                const int bbuf = (term == 1) ? 3 : 2;
                uint64_t da = MAKE_SMEM_DESC(sb + (s * 4 + abuf) * TILE_BYTES);
                uint64_t db = MAKE_SMEM_DESC(sb + (s * 4 + bbuf) * TILE_BYTES);
#pragma unroll
                for (int ks = 0; ks < 4; ks++)
                    mma_tf32_ss(tmem, da + ks * 2, db + ks * 2, IDESC_TF32,
                                (uint32_t)((kt | term | ks) != 0));
            }
            TCGEN05_COMMIT(s ? mb1 : mb0);
        }
    }
    {
        const int f = (nk - 1) & 1;
        if (f == 0) MBARRIER_WAIT_PARITY(mb0, ph0 & 1);
        else        MBARRIER_WAIT_PARITY(mb1, ph1 & 1);
    }
    TCGEN05_FENCE_AFTER();

    if (wid < 4) {
        const int m = m0 + wid * 32 + lid;
        float* crow = C + (size_t)m * N + n0;
#pragma unroll
        for (int c0 = 0; c0 < 128; c0 += 32) {
            uint32_t r[32];
            TCGEN05_LD_32X32B_X32(r, tmem + c0);
            TCGEN05_WAIT_LD();
#pragma unroll
            for (int c = 0; c < 32; c++)
                crow[c0 + c] = __uint_as_float(r[c]) + bias[n0 + c0 + c];
        }
        TCGEN05_FENCE_BEFORE();
    }
    __syncthreads();
    if (wid == 0) TCGEN05_DEALLOC(tmem, 128);

#else  // ---------------- SIMT fp32 fallback (target-portable) ---------------
    __shared__ float As[8][132];
    __shared__ float Bs[8][132];

    const int tid = threadIdx.x;
    const int m0 = blockIdx.y * 128;
    const int n0 = blockIdx.x * 128;
    const int ty = tid >> 4;        // 16 row groups
    const int tx = tid & 15;        // 16 col groups

    float acc[8][8];
#pragma unroll
    for (int i = 0; i < 8; i++)
#pragma unroll
        for (int j = 0; j < 8; j++) acc[i][j] = 0.0f;

    const int lm = tid >> 1;        // 0..127
    const int lk = (tid & 1) * 4;   // 0 or 4

    for (int k0 = 0; k0 < K; k0 += 8) {
        float4 ah = *(const float4*)(Ahi + (size_t)(m0 + lm) * K + k0 + lk);
        float4 al = *(const float4*)(Alo + (size_t)(m0 + lm) * K + k0 + lk);
        float4 bh = *(const float4*)(Bhi + (size_t)(n0 + lm) * K + k0 + lk);
        float4 bl = *(const float4*)(Blo + (size_t)(n0 + lm) * K + k0 + lk);
        As[lk + 0][lm] = ah.x + al.x; As[lk + 1][lm] = ah.y + al.y;
        As[lk + 2][lm] = ah.z + al.z; As[lk + 3][lm] = ah.w + al.w;
        Bs[lk + 0][lm] = bh.x + bl.x; Bs[lk + 1][lm] = bh.y + bl.y;
        Bs[lk + 2][lm] = bh.z + bl.z; Bs[lk + 3][lm] = bh.w + bl.w;
        __syncthreads();
#pragma unroll
        for (int k = 0; k < 8; k++) {
            float ar[8], br[8];
#pragma unroll
            for (int i = 0; i < 8; i++) ar[i] = As[k][ty * 8 + i];
#pragma unroll
            for (int j = 0; j < 8; j++) br[j] = Bs[k][tx * 8 + j];
#pragma unroll
            for (int i = 0; i < 8; i++)
#pragma unroll
                for (int j = 0; j < 8; j++)
                    acc[i][j] = fmaf(ar[i], br[j], acc[i][j]);
        }
        __syncthreads();
    }

#pragma unroll
    for (int i = 0; i < 8; i++) {
        int m = m0 + ty * 8 + i;
#pragma unroll
        for (int j = 0; j < 8; j += 4) {
            float4 o;
            o.x = acc[i][j + 0] + bias[n0 + tx * 8 + j + 0];
            o.y = acc[i][j + 1] + bias[n0 + tx * 8 + j + 1];
            o.z = acc[i][j + 2] + bias[n0 + tx * 8 + j + 2];
            o.w = acc[i][j + 3] + bias[n0 + tx * 8 + j + 3];
            *(float4*)(C + (size_t)m * N + n0 + tx * 8 + j) = o;
        }
    }
#endif
}

// ======================= small kernels ======================================
__global__ void k_split(const float* __restrict__ src, float* __restrict__ hi,
                        float* __restrict__ lo, int n)
{
    int i = blockIdx.x * blockDim.x + threadIdx.x;
    if (i < n) {
        float a = src[i];
        float h = tf32r(a);
        hi[i] = h;
        lo[i] = tf32r(a - h);
    }
}

__global__ void k_init(const float* __restrict__ x, float* __restrict__ out)
{
    int i = blockIdx.x * blockDim.x + threadIdx.x;
    float L = logf(expf(1.0f) + (float)(VV - 1));
    if (i < BB * VV) {
        int b = i / VV, v = i % VV;
        out[(size_t)b * TT * VV + v] = (v == 0 ? 1.0f : 0.0f) - L;
    }
    if (i < BB * HH) {
        float h = x[i];
        g_h[i] = h;
        float hh = tf32r(h);
        g_h_hi[i] = hh;
        g_h_lo[i] = tf32r(h - hh);
    }
    if (i < BB) g_idx[i] = 0;
}

__global__ void k_gates()
{
    int g = blockIdx.x * blockDim.x + threadIdx.x;
    int b = g >> 10;
    int i = g & (HH - 1);
    const float* gi = g_eproj + (size_t)g_idx[b] * H3;
    const float* gh = g_gh + (size_t)b * H3;
    float r = 1.0f / (1.0f + expf(-(gi[i]          + gh[i])));
    float z = 1.0f / (1.0f + expf(-(gi[HH + i]     + gh[HH + i])));
    float n = tanhf(gi[2 * HH + i] + r * gh[2 * HH + i]);
    float hn = (1.0f - z) * n + z * g_h[g];
    g_h[g] = hn;
    float hh = tf32r(hn);
    g_h_hi[g] = hh;
    g_h_lo[g] = tf32r(hn - hh);
}

__global__ __launch_bounds__(1024)
void k_softmax(float* __restrict__ out, int t)
{
    const int b = blockIdx.x;
    const int tid = threadIdx.x;
    const float* row = g_logits + (size_t)b * VV;
    float* orow = out + ((size_t)b * TT + t) * VV;

    __shared__ float s_v[1024];
    __shared__ int   s_i[1024];

    float x[8];
    float mx = -__int_as_float(0x7f800000);
    int   ai = 0;
#pragma unroll
    for (int j = 0; j < 8; j++) {
        int idx = tid + j * 1024;
        x[j] = row[idx];
        if (x[j] > mx) { mx = x[j]; ai = idx; }
    }
    s_v[tid] = mx; s_i[tid] = ai;
    __syncthreads();
#pragma unroll
    for (int s = 512; s > 0; s >>= 1) {
        if (tid < s) {
            float v2 = s_v[tid + s]; int i2 = s_i[tid + s];
            if (v2 > s_v[tid] || (v2 == s_v[tid] && i2 < s_i[tid])) {
                s_v[tid] = v2; s_i[tid] = i2;
            }
        }
        __syncthreads();
    }
    float gmax = s_v[0];
    int   gidx = s_i[0];
    __syncthreads();

    float sum = 0.0f;
#pragma unroll
    for (int j = 0; j < 8; j++) sum += expf(x[j] - gmax);
    s_v[tid] = sum;
    __syncthreads();
#pragma unroll
    for (int s = 512; s > 0; s >>= 1) {
        if (tid < s) s_v[tid] += s_v[tid + s];
        __syncthreads();
    }
    float lse = gmax + logf(s_v[0]);

#pragma unroll
    for (int j = 0; j < 8; j++)
        orow[tid + j * 1024] = x[j] - lse;

    if (tid == 0) g_idx[b] = gidx;
}

// ======================= launch =============================================
extern "C" void kernel_launch(void* const* d_in, const int* in_sizes, int n_in,
                              void* d_out, int out_size)
{
    const float* x     = (const float*)d_in[0];
    const float* emb   = (const float*)d_in[1];
    const float* w_ih  = (const float*)d_in[2];
    const float* w_hh  = (const float*)d_in[3];
    const float* b_ih  = (const float*)d_in[4];
    const float* b_hh  = (const float*)d_in[5];
    const float* cls_w = (const float*)d_in[6];
    const float* cls_b = (const float*)d_in[7];
    float* out = (float*)d_out;

    float *eproj, *hbuf_hi, *hbuf_lo, *ghbuf, *logits;
    float *emb_hi, *emb_lo, *wih_hi, *wih_lo, *whh_hi, *whh_lo, *cls_hi, *cls_lo;
    cudaGetSymbolAddress((void**)&eproj,   g_eproj);
    cudaGetSymbolAddress((void**)&hbuf_hi, g_h_hi);
    cudaGetSymbolAddress((void**)&hbuf_lo, g_h_lo);
    cudaGetSymbolAddress((void**)&ghbuf,   g_gh);
    cudaGetSymbolAddress((void**)&logits,  g_logits);
    cudaGetSymbolAddress((void**)&emb_hi,  g_emb_hi);
    cudaGetSymbolAddress((void**)&emb_lo,  g_emb_lo);
    cudaGetSymbolAddress((void**)&wih_hi,  g_wih_hi);
    cudaGetSymbolAddress((void**)&wih_lo,  g_wih_lo);
    cudaGetSymbolAddress((void**)&whh_hi,  g_whh_hi);
    cudaGetSymbolAddress((void**)&whh_lo,  g_whh_lo);
    cudaGetSymbolAddress((void**)&cls_hi,  g_cls_hi);
    cudaGetSymbolAddress((void**)&cls_lo,  g_cls_lo);

    cudaFuncSetAttribute(k_gemm_tc, cudaFuncAttributeMaxDynamicSharedMemorySize, GEMM_SMEM);

    k_init<<<(BB * VV + 255) / 256, 256>>>(x, out);

    k_split<<<((int)((size_t)VV * EMB) + 255) / 256, 256>>>(emb,   emb_hi, emb_lo, VV * EMB);
    k_split<<<((int)((size_t)H3 * EMB) + 255) / 256, 256>>>(w_ih,  wih_hi, wih_lo, H3 * EMB);
    k_split<<<((int)((size_t)H3 * HH)  + 255) / 256, 256>>>(w_hh,  whh_hi, whh_lo, H3 * HH);
    k_split<<<((int)((size_t)VV * HH)  + 255) / 256, 256>>>(cls_w, cls_hi, cls_lo, VV * HH);

    // E_proj = emb @ w_ih^T + b_ih   [V, 3H]
    k_gemm_tc<<<dim3(H3 / 128, VV / 128), 256, GEMM_SMEM>>>(
        emb_hi, emb_lo, wih_hi, wih_lo, b_ih, eproj, H3, EMB);

    for (int t = 1; t < TT; t++) {
        k_gemm_tc<<<dim3(H3 / 128, 1), 256, GEMM_SMEM>>>(
            hbuf_hi, hbuf_lo, whh_hi, whh_lo, b_hh, ghbuf, H3, HH);
        k_gates<<<(BB * HH) / 256, 256>>>();
        k_gemm_tc<<<dim3(VV / 128, 1), 256, GEMM_SMEM>>>(
            hbuf_hi, hbuf_lo, cls_hi, cls_lo, cls_b, logits, VV, HH);
        k_softmax<<<BB, 1024>>>(out, t);
    }
}

// round 4
// speedup vs baseline: 1.1867x; 1.0480x over previous
#include <cuda_runtime.h>
#include <math.h>
#include <stdint.h>

#define BB  128
#define EMB 512
#define HH  1024
#define H3  3072
#define VV  8192
#define TT  100

// ======================= device scratch (no allocs allowed) ==================
__device__ float g_h[BB * HH];
__device__ float g_h_hi[BB * HH];
__device__ float g_h_lo[BB * HH];
__device__ float g_gh[BB * H3];
__device__ float g_logits[BB * VV];
__device__ int   g_idx[BB];
__device__ float g_eproj[(size_t)VV * H3];
__device__ float g_emb_hi[(size_t)VV * EMB];
__device__ float g_emb_lo[(size_t)VV * EMB];
__device__ float g_wih_hi[(size_t)H3 * EMB];
__device__ float g_wih_lo[(size_t)H3 * EMB];
__device__ float g_whh_hi[(size_t)H3 * HH];
__device__ float g_whh_lo[(size_t)H3 * HH];
__device__ float g_cls_hi[(size_t)VV * HH];
__device__ float g_cls_lo[(size_t)VV * HH];

// ======================= helpers ============================================
__device__ __forceinline__ float tf32r(float a) {
    uint32_t u;
    asm("cvt.rna.tf32.f32 %0, %1;" : "=r"(u) : "f"(a));
    return __uint_as_float(u);
}

__device__ __forceinline__ void mma8(float c[4], const float a[4], const float b[2]) {
    asm volatile(
        "mma.sync.aligned.m16n8k8.row.col.f32.tf32.tf32.f32 "
        "{%0,%1,%2,%3}, {%4,%5,%6,%7}, {%8,%9}, {%0,%1,%2,%3};"
        : "+f"(c[0]), "+f"(c[1]), "+f"(c[2]), "+f"(c[3])
        : "r"(__float_as_uint(a[0])), "r"(__float_as_uint(a[1])),
          "r"(__float_as_uint(a[2])), "r"(__float_as_uint(a[3])),
          "r"(__float_as_uint(b[0])), "r"(__float_as_uint(b[1])));
}

// ======================= mma.sync 3xTF32 GEMM ================================
// Computes up to two targets in one launch:
//   target1 (tile ids [0, nT1)):        C1[M,N1] = A @ B1^T + bias1
//   target2 (tile ids [nT1, grid)):     C2[M,N2] = A @ B2^T + bias2
// A = (Ahi + Alo)[M,K] row-major; Bx = (Bxhi + Bxlo)[Nx,K] row-major.
// CTA tile 64x64, BK=16, 256 threads, warp tile 16x32 (4 m-warps x 2 n-warps).
#define BK 16
#define SMS 20   // padded floats per smem row

__global__ __launch_bounds__(256, 2)
void k_gemm_mma(const float* __restrict__ Ahi, const float* __restrict__ Alo,
                const float* __restrict__ B1hi, const float* __restrict__ B1lo,
                const float* __restrict__ bias1, float* __restrict__ C1,
                int N1, int nT1,
                const float* __restrict__ B2hi, const float* __restrict__ B2lo,
                const float* __restrict__ bias2, float* __restrict__ C2,
                int N2, int K)
{
    __shared__ float sA[2][2][64 * SMS];   // [stage][hi/lo][row*SMS+k]
    __shared__ float sB[2][2][64 * SMS];

    const int tid  = threadIdx.x;
    const int wid  = tid >> 5, lane = tid & 31;
    const int grp  = lane >> 2, tig = lane & 3;
    const int wm   = wid & 3, wn = wid >> 2;
    const int mo   = wm * 16, no = wn * 32;

    // decode tile
    int id = blockIdx.x;
    const float *Bhi, *Blo, *bias; float* C; int N;
    if (id < nT1) { Bhi = B1hi; Blo = B1lo; bias = bias1; C = C1; N = N1; }
    else { id -= nT1; Bhi = B2hi; Blo = B2lo; bias = bias2; C = C2; N = N2; }
    const int ntn = N >> 6;
    const int tn = id % ntn, tm = id / ntn;
    const int m0 = tm << 6, n0 = tn << 6;

    // gmem load: each thread loads one float4 from each of the 4 matrices
    const int lrow = tid >> 2;          // 0..63
    const int lcol = (tid & 3) << 2;    // 0,4,8,12
    const float* pAh = Ahi + (size_t)(m0 + lrow) * K + lcol;
    const float* pAl = Alo + (size_t)(m0 + lrow) * K + lcol;
    const float* pBh = Bhi + (size_t)(n0 + lrow) * K + lcol;
    const float* pBl = Blo + (size_t)(n0 + lrow) * K + lcol;
    const int soff = lrow * SMS + lcol;

    float c[4][4];
#pragma unroll
    for (int j = 0; j < 4; j++)
#pragma unroll
        for (int i = 0; i < 4; i++) c[j][i] = 0.0f;

    const int nk = K / BK;

    float4 va0 = *(const float4*)pAh;
    float4 va1 = *(const float4*)pAl;
    float4 vb0 = *(const float4*)pBh;
    float4 vb1 = *(const float4*)pBl;
    *(float4*)&sA[0][0][soff] = va0;
    *(float4*)&sA[0][1][soff] = va1;
    *(float4*)&sB[0][0][soff] = vb0;
    *(float4*)&sB[0][1][soff] = vb1;
    __syncthreads();

    for (int kt = 0; kt < nk; kt++) {
        const int s = kt & 1;
        if (kt + 1 < nk) {
            const int off = (kt + 1) * BK;
            va0 = *(const float4*)(pAh + off);
            va1 = *(const float4*)(pAl + off);
            vb0 = *(const float4*)(pBh + off);
            vb1 = *(const float4*)(pBl + off);
        }
#pragma unroll
        for (int ks = 0; ks < 2; ks++) {
            const int k0 = ks * 8;
            float ah[4], al[4];
            const int ra = (mo + grp) * SMS + k0 + tig;
            const int rb = (mo + grp + 8) * SMS + k0 + tig;
            ah[0] = sA[s][0][ra];     ah[1] = sA[s][0][rb];
            ah[2] = sA[s][0][ra + 4]; ah[3] = sA[s][0][rb + 4];
            al[0] = sA[s][1][ra];     al[1] = sA[s][1][rb];
            al[2] = sA[s][1][ra + 4]; al[3] = sA[s][1][rb + 4];
#pragma unroll
            for (int j = 0; j < 4; j++) {
                float bh[2], bl[2];
                const int rn = (no + j * 8 + grp) * SMS + k0 + tig;
                bh[0] = sB[s][0][rn]; bh[1] = sB[s][0][rn + 4];
                bl[0] = sB[s][1][rn]; bl[1] = sB[s][1][rn + 4];
                mma8(c[j], ah, bh);   // hi*hi
                mma8(c[j], ah, bl);   // hi*lo
                mma8(c[j], al, bh);   // lo*hi
            }
        }
        if (kt + 1 < nk) {
            const int s1 = s ^ 1;
            *(float4*)&sA[s1][0][soff] = va0;
            *(float4*)&sA[s1][1][soff] = va1;
            *(float4*)&sB[s1][0][soff] = vb0;
            *(float4*)&sB[s1][1][soff] = vb1;
            __syncthreads();
        }
    }

    // epilogue
#pragma unroll
    for (int j = 0; j < 4; j++) {
        const int col = n0 + no + j * 8 + 2 * tig;
        const int r0 = m0 + mo + grp, r1 = r0 + 8;
        const float b0v = bias[col], b1v = bias[col + 1];
        C[(size_t)r0 * N + col]     = c[j][0] + b0v;
        C[(size_t)r0 * N + col + 1] = c[j][1] + b1v;
        C[(size_t)r1 * N + col]     = c[j][2] + b0v;
        C[(size_t)r1 * N + col + 1] = c[j][3] + b1v;
    }
}

// ======================= small kernels ======================================
__global__ void k_split(const float* __restrict__ src, float* __restrict__ hi,
                        float* __restrict__ lo, int n)
{
    int i = blockIdx.x * blockDim.x + threadIdx.x;
    if (i < n) {
        float a = src[i];
        float h = tf32r(a);
        hi[i] = h;
        lo[i] = tf32r(a - h);
    }
}

__global__ void k_init(const float* __restrict__ x, float* __restrict__ out)
{
    int i = blockIdx.x * blockDim.x + threadIdx.x;
    float L = logf(expf(1.0f) + (float)(VV - 1));
    if (i < BB * VV) {
        int b = i / VV, v = i % VV;
        out[(size_t)b * TT * VV + v] = (v == 0 ? 1.0f : 0.0f) - L;
    }
    if (i < BB * HH) {
        float h = x[i];
        g_h[i] = h;
        float hh = tf32r(h);
        g_h_hi[i] = hh;
        g_h_lo[i] = tf32r(h - hh);
    }
    if (i < BB) g_idx[i] = 0;
}

__global__ void k_gates()
{
    int g = blockIdx.x * blockDim.x + threadIdx.x;
    int b = g >> 10;
    int i = g & (HH - 1);
    const float* gi = g_eproj + (size_t)g_idx[b] * H3;
    const float* gh = g_gh + (size_t)b * H3;
    float r = 1.0f / (1.0f + expf(-(gi[i]          + gh[i])));
    float z = 1.0f / (1.0f + expf(-(gi[HH + i]     + gh[HH + i])));
    float n = tanhf(gi[2 * HH + i] + r * gh[2 * HH + i]);
    float hn = (1.0f - z) * n + z * g_h[g];
    g_h[g] = hn;
    float hh = tf32r(hn);
    g_h_hi[g] = hh;
    g_h_lo[g] = tf32r(hn - hh);
}

__global__ __launch_bounds__(1024)
void k_softmax(float* __restrict__ out, int t)
{
    const int b = blockIdx.x;
    const int tid = threadIdx.x;
    const float* row = g_logits + (size_t)b * VV;
    float* orow = out + ((size_t)b * TT + t) * VV;

    __shared__ float s_v[1024];
    __shared__ int   s_i[1024];

    float x[8];
    float mx = -__int_as_float(0x7f800000);
    int   ai = 0;
#pragma unroll
    for (int j = 0; j < 8; j++) {
        int idx = tid + j * 1024;
        x[j] = row[idx];
        if (x[j] > mx) { mx = x[j]; ai = idx; }
    }
    s_v[tid] = mx; s_i[tid] = ai;
    __syncthreads();
#pragma unroll
    for (int s = 512; s > 0; s >>= 1) {
        if (tid < s) {
            float v2 = s_v[tid + s]; int i2 = s_i[tid + s];
            if (v2 > s_v[tid] || (v2 == s_v[tid] && i2 < s_i[tid])) {
                s_v[tid] = v2; s_i[tid] = i2;
            }
        }
        __syncthreads();
    }
    float gmax = s_v[0];
    int   gidx = s_i[0];
    __syncthreads();

    float sum = 0.0f;
#pragma unroll
    for (int j = 0; j < 8; j++) sum += expf(x[j] - gmax);
    s_v[tid] = sum;
    __syncthreads();
#pragma unroll
    for (int s = 512; s > 0; s >>= 1) {
        if (tid < s) s_v[tid] += s_v[tid + s];
        __syncthreads();
    }
    float lse = gmax + logf(s_v[0]);

#pragma unroll
    for (int j = 0; j < 8; j++)
        orow[tid + j * 1024] = x[j] - lse;

    if (tid == 0) g_idx[b] = gidx;
}

// ======================= launch =============================================
extern "C" void kernel_launch(void* const* d_in, const int* in_sizes, int n_in,
                              void* d_out, int out_size)
{
    const float* x     = (const float*)d_in[0];
    const float* emb   = (const float*)d_in[1];
    const float* w_ih  = (const float*)d_in[2];
    const float* w_hh  = (const float*)d_in[3];
    const float* b_ih  = (const float*)d_in[4];
    const float* b_hh  = (const float*)d_in[5];
    const float* cls_w = (const float*)d_in[6];
    const float* cls_b = (const float*)d_in[7];
    float* out = (float*)d_out;

    float *eproj, *h_hi, *h_lo, *ghbuf, *logits;
    float *emb_hi, *emb_lo, *wih_hi, *wih_lo, *whh_hi, *whh_lo, *cls_hi, *cls_lo;
    cudaGetSymbolAddress((void**)&eproj,  g_eproj);
    cudaGetSymbolAddress((void**)&h_hi,   g_h_hi);
    cudaGetSymbolAddress((void**)&h_lo,   g_h_lo);
    cudaGetSymbolAddress((void**)&ghbuf,  g_gh);
    cudaGetSymbolAddress((void**)&logits, g_logits);
    cudaGetSymbolAddress((void**)&emb_hi, g_emb_hi);
    cudaGetSymbolAddress((void**)&emb_lo, g_emb_lo);
    cudaGetSymbolAddress((void**)&wih_hi, g_wih_hi);
    cudaGetSymbolAddress((void**)&wih_lo, g_wih_lo);
    cudaGetSymbolAddress((void**)&whh_hi, g_whh_hi);
    cudaGetSymbolAddress((void**)&whh_lo, g_whh_lo);
    cudaGetSymbolAddress((void**)&cls_hi, g_cls_hi);
    cudaGetSymbolAddress((void**)&cls_lo, g_cls_lo);

    k_init<<<(BB * VV + 255) / 256, 256>>>(x, out);

    k_split<<<(VV * EMB + 255) / 256, 256>>>(emb,   emb_hi, emb_lo, VV * EMB);
    k_split<<<(H3 * EMB + 255) / 256, 256>>>(w_ih,  wih_hi, wih_lo, H3 * EMB);
    k_split<<<(H3 * HH  + 255) / 256, 256>>>(w_hh,  whh_hi, whh_lo, H3 * HH);
    k_split<<<(VV * HH  + 255) / 256, 256>>>(cls_w, cls_hi, cls_lo, VV * HH);

    // E_proj = emb @ w_ih^T + b_ih   [V, 3H]  (single target, K=EMB)
    {
        const int nT = (H3 / 64) * (VV / 64);      // 6144
        k_gemm_mma<<<nT, 256>>>(emb_hi, emb_lo,
                                wih_hi, wih_lo, b_ih, eproj, H3, nT,
                                wih_hi, wih_lo, b_ih, eproj, H3, EMB);
    }

    const int nGh  = (H3 / 64) * (BB / 64);        // 96
    const int nCls = (VV / 64) * (BB / 64);        // 256

    // gh(1) = h0 @ w_hh^T + b_hh  (gh-only: grid = nGh)
    k_gemm_mma<<<nGh, 256>>>(h_hi, h_lo,
                             whh_hi, whh_lo, b_hh, ghbuf, H3, nGh,
                             cls_hi, cls_lo, cls_b, logits, VV, HH);

    for (int t = 1; t < TT; t++) {
        // h_t = GRU(eproj[idx_{t-1}], gh_t, h_{t-1})  (+ tf32 re-split)
        k_gates<<<(BB * HH) / 256, 256>>>();
        // fused: gh(t+1) = h_t @ w_hh^T  AND  logits(t) = h_t @ cls_w^T
        k_gemm_mma<<<nGh + nCls, 256>>>(h_hi, h_lo,
                                        whh_hi, whh_lo, b_hh, ghbuf, H3, nGh,
                                        cls_hi, cls_lo, cls_b, logits, VV, HH);
        // out[:,t,:] = log_softmax(logits); idx_t = argmax
        k_softmax<<<BB, 1024>>>(out, t);
    }
}

// round 5
// speedup vs baseline: 2.4226x; 2.0415x over previous
#include <cuda_runtime.h>
#include <cuda_fp16.h>
#include <math.h>
#include <stdint.h>

#define BB  128
#define EMB 512
#define HH  1024
#define H3  3072
#define VV  8192
#define TT  100

#define LO_SCALE   2048.0f
#define LO_INV     (1.0f / 2048.0f)

// ======================= device scratch (no allocs allowed) ==================
__device__ float g_h[BB * HH];
__device__ float g_gh[BB * H3];
__device__ float g_logits[BB * VV];
__device__ int   g_idx[BB];
__device__ float g_eproj[(size_t)VV * H3];

__device__ __align__(128) __half g_h_hi[BB * HH];
__device__ __align__(128) __half g_h_lo[BB * HH];
__device__ __align__(128) __half g_emb_hi[(size_t)VV * EMB];
__device__ __align__(128) __half g_emb_lo[(size_t)VV * EMB];
__device__ __align__(128) __half g_wih_hi[(size_t)H3 * EMB];
__device__ __align__(128) __half g_wih_lo[(size_t)H3 * EMB];
__device__ __align__(128) __half g_whh_hi[(size_t)H3 * HH];
__device__ __align__(128) __half g_whh_lo[(size_t)H3 * HH];
__device__ __align__(128) __half g_cls_hi[(size_t)VV * HH];
__device__ __align__(128) __half g_cls_lo[(size_t)VV * HH];

// ======================= helpers ============================================
__device__ __forceinline__ uint32_t smem_u32(const void* p) {
    uint32_t a;
    asm("{ .reg .u64 t; cvta.to.shared.u64 t, %1; cvt.u32.u64 %0, t; }"
        : "=r"(a) : "l"(p));
    return a;
}
__device__ __forceinline__ void cpasync16(uint32_t dst, const void* src) {
    asm volatile("cp.async.cg.shared.global [%0], [%1], 16;"
                 :: "r"(dst), "l"(src) : "memory");
}
#define CP_COMMIT() asm volatile("cp.async.commit_group;" ::: "memory")

__device__ __forceinline__ void mma16(float c[4], const uint32_t a[4], const uint32_t b[2]) {
    asm volatile(
        "mma.sync.aligned.m16n8k16.row.col.f32.f16.f16.f32 "
        "{%0,%1,%2,%3}, {%4,%5,%6,%7}, {%8,%9}, {%0,%1,%2,%3};"
        : "+f"(c[0]), "+f"(c[1]), "+f"(c[2]), "+f"(c[3])
        : "r"(a[0]), "r"(a[1]), "r"(a[2]), "r"(a[3]), "r"(b[0]), "r"(b[1]));
}

// ======================= fp16 split-precision GEMM ===========================
// C[M,N] = (Ahi + Alo*2^-11)[M,K] @ (Bhi + Blo*2^-11)[N,K]^T + bias[N]
// Two fused targets: tile ids [0,nT1) -> target1, rest -> target2.
// CTA tile 128x128, BK=32, 256 threads (8 warps: 4 m-warps x 2 n-warps,
// warp tile 32x64), 3-stage cp.async pipeline.
#define SROW        40                    // halfs per smem row (pad 32->40)
#define PLANE_H     (128 * SROW)          // halfs per plane
#define PLANE_B     (PLANE_H * 2)         // bytes per plane   (10240)
#define STAGE_H     (4 * PLANE_H)
#define STAGE_B     (4 * PLANE_B)         // 40960
#define NSTAGE      3
#define GEMM_SMEM_B (NSTAGE * STAGE_B)    // 122880

__global__ __launch_bounds__(256, 1)
void k_gemm_h(const __half* __restrict__ Ahi, const __half* __restrict__ Alo,
              const __half* __restrict__ B1hi, const __half* __restrict__ B1lo,
              const float* __restrict__ bias1, float* __restrict__ C1,
              int N1, int nT1,
              const __half* __restrict__ B2hi, const __half* __restrict__ B2lo,
              const float* __restrict__ bias2, float* __restrict__ C2,
              int N2, int K)
{
    extern __shared__ __half smh[];
    const uint32_t sb = smem_u32(smh);

    const int tid  = threadIdx.x;
    const int wid  = tid >> 5, lane = tid & 31;
    const int grp  = lane >> 2, tig = lane & 3;
    const int wm   = wid & 3;             // 4 m-warps
    const int wn   = wid >> 2;            // 2 n-warps
    const int mo   = wm * 32, no = wn * 64;

    // decode tile
    int id = blockIdx.x;
    const __half *Bhi, *Blo; const float* bias; float* C; int N;
    if (id < nT1) { Bhi = B1hi; Blo = B1lo; bias = bias1; C = C1; N = N1; }
    else { id -= nT1; Bhi = B2hi; Blo = B2lo; bias = bias2; C = C2; N = N2; }
    const int ntn = N >> 7;
    const int tn = id % ntn, tm = id / ntn;
    const int m0 = tm << 7, n0 = tn << 7;

    const __half* gp[4];
    gp[0] = Ahi + (size_t)m0 * K;
    gp[1] = Alo + (size_t)m0 * K;
    gp[2] = Bhi + (size_t)n0 * K;
    gp[3] = Blo + (size_t)n0 * K;

    // per-thread load chunks: chunk c (0..511): row=c>>2, kp=c&3 (16B piece)
    const int r0c = tid >> 2,        kp0 = tid & 3;
    const int r1c = (tid + 256) >> 2, kp1 = (tid + 256) & 3;

    const int nk = K >> 5;

    // accumulators
    float cm[2][8][4], cl[2][8][4];
#pragma unroll
    for (int mb = 0; mb < 2; mb++)
#pragma unroll
        for (int j = 0; j < 8; j++)
#pragma unroll
            for (int i = 0; i < 4; i++) { cm[mb][j][i] = 0.0f; cl[mb][j][i] = 0.0f; }

    // ---- load stage helper (macro-ish via lambda) ----
    auto load_stage = [&](int kt, int st) {
        const int koff = kt << 5;
        const uint32_t base = sb + st * STAGE_B;
#pragma unroll
        for (int p = 0; p < 4; p++) {
            cpasync16(base + p * PLANE_B + r0c * (SROW * 2) + kp0 * 16,
                      gp[p] + (size_t)r0c * K + koff + kp0 * 8);
            cpasync16(base + p * PLANE_B + r1c * (SROW * 2) + kp1 * 16,
                      gp[p] + (size_t)r1c * K + koff + kp1 * 8);
        }
        CP_COMMIT();
    };

    load_stage(0, 0);
    load_stage(1, 1);

    for (int kt = 0; kt < nk; kt++) {
        if (kt + 1 < nk) asm volatile("cp.async.wait_group 1;" ::: "memory");
        else             asm volatile("cp.async.wait_group 0;" ::: "memory");
        __syncthreads();
        if (kt + 2 < nk) load_stage(kt + 2, (kt + 2) % NSTAGE);

        const int st = kt % NSTAGE;
        const __half* sAhi = smh + st * STAGE_H;
        const __half* sAlo = sAhi + PLANE_H;
        const __half* sBhi = sAlo + PLANE_H;
        const __half* sBlo = sBhi + PLANE_H;

#pragma unroll
        for (int ks = 0; ks < 2; ks++) {
            const int kb = ks * 16 + 2 * tig;
            uint32_t ah[2][4], al[2][4];
#pragma unroll
            for (int mb = 0; mb < 2; mb++) {
                const int r = mo + mb * 16 + grp;
                ah[mb][0] = *(const uint32_t*)(sAhi + r * SROW + kb);
                ah[mb][1] = *(const uint32_t*)(sAhi + (r + 8) * SROW + kb);
                ah[mb][2] = *(const uint32_t*)(sAhi + r * SROW + kb + 8);
                ah[mb][3] = *(const uint32_t*)(sAhi + (r + 8) * SROW + kb + 8);
                al[mb][0] = *(const uint32_t*)(sAlo + r * SROW + kb);
                al[mb][1] = *(const uint32_t*)(sAlo + (r + 8) * SROW + kb);
                al[mb][2] = *(const uint32_t*)(sAlo + r * SROW + kb + 8);
                al[mb][3] = *(const uint32_t*)(sAlo + (r + 8) * SROW + kb + 8);
            }
#pragma unroll
            for (int j = 0; j < 8; j++) {
                const int n = no + j * 8 + grp;
                uint32_t bh[2], bl[2];
                bh[0] = *(const uint32_t*)(sBhi + n * SROW + kb);
                bh[1] = *(const uint32_t*)(sBhi + n * SROW + kb + 8);
                bl[0] = *(const uint32_t*)(sBlo + n * SROW + kb);
                bl[1] = *(const uint32_t*)(sBlo + n * SROW + kb + 8);
#pragma unroll
                for (int mb = 0; mb < 2; mb++) {
                    mma16(cm[mb][j], ah[mb], bh);   // hi*hi
                    mma16(cl[mb][j], ah[mb], bl);   // hi*lo'
                    mma16(cl[mb][j], al[mb], bh);   // lo'*hi
                }
            }
        }
        __syncthreads();
    }

    // epilogue: C = cm + cl*2^-11 + bias
#pragma unroll
    for (int mb = 0; mb < 2; mb++) {
#pragma unroll
        for (int j = 0; j < 8; j++) {
            const int col = n0 + no + j * 8 + 2 * tig;
            const int r0 = m0 + mo + mb * 16 + grp;
            const int r1 = r0 + 8;
            const float b0 = bias[col], b1 = bias[col + 1];
            float2 v0, v1;
            v0.x = cm[mb][j][0] + cl[mb][j][0] * LO_INV + b0;
            v0.y = cm[mb][j][1] + cl[mb][j][1] * LO_INV + b1;
            v1.x = cm[mb][j][2] + cl[mb][j][2] * LO_INV + b0;
            v1.y = cm[mb][j][3] + cl[mb][j][3] * LO_INV + b1;
            *(float2*)(C + (size_t)r0 * N + col) = v0;
            *(float2*)(C + (size_t)r1 * N + col) = v1;
        }
    }
}

// ======================= small kernels ======================================
__device__ __forceinline__ void split_h(float a, __half* hi, __half* lo) {
    __half h = __float2half_rn(a);
    float r = a - __half2float(h);
    *hi = h;
    *lo = __float2half_rn(r * LO_SCALE);
}

__global__ void k_split(const float* __restrict__ src, __half* __restrict__ hi,
                        __half* __restrict__ lo, int n)
{
    int i = blockIdx.x * blockDim.x + threadIdx.x;
    if (i < n) split_h(src[i], hi + i, lo + i);
}

__global__ void k_init(const float* __restrict__ x, float* __restrict__ out)
{
    int i = blockIdx.x * blockDim.x + threadIdx.x;
    float L = logf(expf(1.0f) + (float)(VV - 1));
    if (i < BB * VV) {
        int b = i / VV, v = i % VV;
        out[(size_t)b * TT * VV + v] = (v == 0 ? 1.0f : 0.0f) - L;
    }
    if (i < BB * HH) {
        float h = x[i];
        g_h[i] = h;
        split_h(h, g_h_hi + i, g_h_lo + i);
    }
    if (i < BB) g_idx[i] = 0;
}

__global__ void k_gates()
{
    int g = blockIdx.x * blockDim.x + threadIdx.x;
    int b = g >> 10;
    int i = g & (HH - 1);
    const float* gi = g_eproj + (size_t)g_idx[b] * H3;
    const float* gh = g_gh + (size_t)b * H3;
    float r = 1.0f / (1.0f + expf(-(gi[i]          + gh[i])));
    float z = 1.0f / (1.0f + expf(-(gi[HH + i]     + gh[HH + i])));
    float n = tanhf(gi[2 * HH + i] + r * gh[2 * HH + i]);
    float hn = (1.0f - z) * n + z * g_h[g];
    g_h[g] = hn;
    split_h(hn, g_h_hi + g, g_h_lo + g);
}

__global__ __launch_bounds__(1024)
void k_softmax(float* __restrict__ out, int t)
{
    const int b = blockIdx.x;
    const int tid = threadIdx.x;
    const float* row = g_logits + (size_t)b * VV;
    float* orow = out + ((size_t)b * TT + t) * VV;

    __shared__ float s_v[1024];
    __shared__ int   s_i[1024];

    float x[8];
    float mx = -__int_as_float(0x7f800000);
    int   ai = 0;
#pragma unroll
    for (int j = 0; j < 8; j++) {
        int idx = tid + j * 1024;
        x[j] = row[idx];
        if (x[j] > mx) { mx = x[j]; ai = idx; }
    }
    s_v[tid] = mx; s_i[tid] = ai;
    __syncthreads();
#pragma unroll
    for (int s = 512; s > 0; s >>= 1) {
        if (tid < s) {
            float v2 = s_v[tid + s]; int i2 = s_i[tid + s];
            if (v2 > s_v[tid] || (v2 == s_v[tid] && i2 < s_i[tid])) {
                s_v[tid] = v2; s_i[tid] = i2;
            }
        }
        __syncthreads();
    }
    float gmax = s_v[0];
    int   gidx = s_i[0];
    __syncthreads();

    float sum = 0.0f;
#pragma unroll
    for (int j = 0; j < 8; j++) sum += expf(x[j] - gmax);
    s_v[tid] = sum;
    __syncthreads();
#pragma unroll
    for (int s = 512; s > 0; s >>= 1) {
        if (tid < s) s_v[tid] += s_v[tid + s];
        __syncthreads();
    }
    float lse = gmax + logf(s_v[0]);

#pragma unroll
    for (int j = 0; j < 8; j++)
        orow[tid + j * 1024] = x[j] - lse;

    if (tid == 0) g_idx[b] = gidx;
}

// ======================= launch =============================================
extern "C" void kernel_launch(void* const* d_in, const int* in_sizes, int n_in,
                              void* d_out, int out_size)
{
    const float* x     = (const float*)d_in[0];
    const float* emb   = (const float*)d_in[1];
    const float* w_ih  = (const float*)d_in[2];
    const float* w_hh  = (const float*)d_in[3];
    const float* b_ih  = (const float*)d_in[4];
    const float* b_hh  = (const float*)d_in[5];
    const float* cls_w = (const float*)d_in[6];
    const float* cls_b = (const float*)d_in[7];
    float* out = (float*)d_out;

    float *eproj, *ghbuf, *logits;
    __half *h_hi, *h_lo, *emb_hi, *emb_lo, *wih_hi, *wih_lo,
           *whh_hi, *whh_lo, *cls_hi, *cls_lo;
    cudaGetSymbolAddress((void**)&eproj,  g_eproj);
    cudaGetSymbolAddress((void**)&ghbuf,  g_gh);
    cudaGetSymbolAddress((void**)&logits, g_logits);
    cudaGetSymbolAddress((void**)&h_hi,   g_h_hi);
    cudaGetSymbolAddress((void**)&h_lo,   g_h_lo);
    cudaGetSymbolAddress((void**)&emb_hi, g_emb_hi);
    cudaGetSymbolAddress((void**)&emb_lo, g_emb_lo);
    cudaGetSymbolAddress((void**)&wih_hi, g_wih_hi);
    cudaGetSymbolAddress((void**)&wih_lo, g_wih_lo);
    cudaGetSymbolAddress((void**)&whh_hi, g_whh_hi);
    cudaGetSymbolAddress((void**)&whh_lo, g_whh_lo);
    cudaGetSymbolAddress((void**)&cls_hi, g_cls_hi);
    cudaGetSymbolAddress((void**)&cls_lo, g_cls_lo);

    cudaFuncSetAttribute(k_gemm_h, cudaFuncAttributeMaxDynamicSharedMemorySize,
                         GEMM_SMEM_B);

    k_init<<<(BB * VV + 255) / 256, 256>>>(x, out);

    k_split<<<(VV * EMB + 255) / 256, 256>>>(emb,   emb_hi, emb_lo, VV * EMB);
    k_split<<<(H3 * EMB + 255) / 256, 256>>>(w_ih,  wih_hi, wih_lo, H3 * EMB);
    k_split<<<(H3 * HH  + 255) / 256, 256>>>(w_hh,  whh_hi, whh_lo, H3 * HH);
    k_split<<<(VV * HH  + 255) / 256, 256>>>(cls_w, cls_hi, cls_lo, VV * HH);

    // E_proj = emb @ w_ih^T + b_ih   [V, 3H],  K = EMB
    {
        const int nT = (VV / 128) * (H3 / 128);     // 64*24 = 1536
        k_gemm_h<<<nT, 256, GEMM_SMEM_B>>>(
            emb_hi, emb_lo,
            wih_hi, wih_lo, b_ih, eproj, H3, nT,
            wih_hi, wih_lo, b_ih, eproj, H3, EMB);
    }

    const int nGh  = H3 / 128;      // 24  (M = 128 -> 1 row tile)
    const int nCls = VV / 128;      // 64

    // gh(1) = h0 @ w_hh^T + b_hh
    k_gemm_h<<<nGh, 256, GEMM_SMEM_B>>>(
        h_hi, h_lo,
        whh_hi, whh_lo, b_hh, ghbuf, H3, nGh,
        cls_hi, cls_lo, cls_b, logits, VV, HH);

    for (int t = 1; t < TT; t++) {
        // h_t = GRU(eproj[idx_{t-1}], gh_t, h_{t-1})  (+ fp16 re-split)
        k_gates<<<(BB * HH) / 256, 256>>>();
        // fused: gh(t+1) = h_t @ w_hh^T  AND  logits(t) = h_t @ cls_w^T
        k_gemm_h<<<nGh + nCls, 256, GEMM_SMEM_B>>>(
            h_hi, h_lo,
            whh_hi, whh_lo, b_hh, ghbuf, H3, nGh,
            cls_hi, cls_lo, cls_b, logits, VV, HH);
        // out[:,t,:] = log_softmax(logits); idx_t = argmax
        k_softmax<<<BB, 1024>>>(out, t);
    }
}

// round 6
// speedup vs baseline: 3.1320x; 1.2928x over previous
#include <cuda_runtime.h>
#include <cuda_fp16.h>
#include <math.h>
#include <stdint.h>

#define BB  128
#define EMB 512
#define HH  1024
#define H3  3072
#define VV  8192
#define TT  100

#define LO_SCALE   2048.0f
#define LO_INV     (1.0f / 2048.0f)

#define NSPLIT  3
#define LSTRIDE (BB * VV)     // logits partial stride
#define GSTRIDE (BB * H3)     // gh partial stride

// ======================= device scratch (no allocs allowed) ==================
__device__ float g_h[BB * HH];
__device__ int   g_idx[BB];
__device__ float g_eproj[(size_t)VV * H3];
__device__ float g_gh_p[NSPLIT * BB * H3];
__device__ float g_logits_p[NSPLIT * BB * VV];

__device__ __align__(128) __half g_h_hi[BB * HH];
__device__ __align__(128) __half g_h_lo[BB * HH];
__device__ __align__(128) __half g_emb_hi[(size_t)VV * EMB];
__device__ __align__(128) __half g_emb_lo[(size_t)VV * EMB];
__device__ __align__(128) __half g_wih_hi[(size_t)H3 * EMB];
__device__ __align__(128) __half g_wih_lo[(size_t)H3 * EMB];
__device__ __align__(128) __half g_whh_hi[(size_t)H3 * HH];
__device__ __align__(128) __half g_whh_lo[(size_t)H3 * HH];
__device__ __align__(128) __half g_cls_hi[(size_t)VV * HH];
__device__ __align__(128) __half g_cls_lo[(size_t)VV * HH];

// ======================= helpers ============================================
__device__ __forceinline__ uint32_t smem_u32(const void* p) {
    uint32_t a;
    asm("{ .reg .u64 t; cvta.to.shared.u64 t, %1; cvt.u32.u64 %0, t; }"
        : "=r"(a) : "l"(p));
    return a;
}
__device__ __forceinline__ void cpasync16(uint32_t dst, const void* src) {
    asm volatile("cp.async.cg.shared.global [%0], [%1], 16;"
                 :: "r"(dst), "l"(src) : "memory");
}
#define CP_COMMIT() asm volatile("cp.async.commit_group;" ::: "memory")

__device__ __forceinline__ void mma16(float c[4], const uint32_t a[4], const uint32_t b[2]) {
    asm volatile(
        "mma.sync.aligned.m16n8k16.row.col.f32.f16.f16.f32 "
        "{%0,%1,%2,%3}, {%4,%5,%6,%7}, {%8,%9}, {%0,%1,%2,%3};"
        : "+f"(c[0]), "+f"(c[1]), "+f"(c[2]), "+f"(c[3])
        : "r"(a[0]), "r"(a[1]), "r"(a[2]), "r"(a[3]), "r"(b[0]), "r"(b[1]));
}

// ======================= fp16 split-precision GEMM (split-K) =================
// C_s[M,N] = (Ahi + Alo*2^-11)[M,Ks] @ (Bhi + Blo*2^-11)[N,Ks]^T  (no bias)
// grid = nsplit * nTiles;  split s writes C + s*splitStride.
// Two targets: tile ids [0,nT1) -> target1, rest -> target2.
// CTA tile 128x128, BK=32, 256 threads, 3-stage cp.async pipeline.
#define SROW        40
#define PLANE_H     (128 * SROW)
#define PLANE_B     (PLANE_H * 2)
#define STAGE_H     (4 * PLANE_H)
#define STAGE_B     (4 * PLANE_B)
#define NSTAGE      3
#define GEMM_SMEM_B (NSTAGE * STAGE_B)

__global__ __launch_bounds__(256, 1)
void k_gemm_h(const __half* __restrict__ Ahi, const __half* __restrict__ Alo,
              const __half* __restrict__ B1hi, const __half* __restrict__ B1lo,
              float* __restrict__ C1, int N1, int nT1, int stride1,
              const __half* __restrict__ B2hi, const __half* __restrict__ B2lo,
              float* __restrict__ C2, int N2, int stride2,
              int K, int nTiles, int ktPer)
{
    extern __shared__ __half smh[];
    const uint32_t sb = smem_u32(smh);

    const int tid  = threadIdx.x;
    const int wid  = tid >> 5, lane = tid & 31;
    const int grp  = lane >> 2, tig = lane & 3;
    const int wm   = wid & 3, wn = wid >> 2;
    const int mo   = wm * 32, no = wn * 64;

    // decode split + tile
    const int sK = blockIdx.x / nTiles;
    int id = blockIdx.x % nTiles;
    const __half *Bhi, *Blo; float* C; int N;
    if (id < nT1) { Bhi = B1hi; Blo = B1lo; C = C1 + (size_t)sK * stride1; N = N1; }
    else { id -= nT1; Bhi = B2hi; Blo = B2lo; C = C2 + (size_t)sK * stride2; N = N2; }
    const int ntn = N >> 7;
    const int tn = id % ntn, tm = id / ntn;
    const int m0 = tm << 7, n0 = tn << 7;

    const int nkAll = K >> 5;
    const int kt0 = sK * ktPer;
    const int nk = min(ktPer, nkAll - kt0);

    const __half* gp[4];
    gp[0] = Ahi + (size_t)m0 * K + (kt0 << 5);
    gp[1] = Alo + (size_t)m0 * K + (kt0 << 5);
    gp[2] = Bhi + (size_t)n0 * K + (kt0 << 5);
    gp[3] = Blo + (size_t)n0 * K + (kt0 << 5);

    const int r0c = tid >> 2,         kp0 = tid & 3;
    const int r1c = (tid + 256) >> 2, kp1 = (tid + 256) & 3;

    float cm[2][8][4], cl[2][8][4];
#pragma unroll
    for (int mb = 0; mb < 2; mb++)
#pragma unroll
        for (int j = 0; j < 8; j++)
#pragma unroll
            for (int i = 0; i < 4; i++) { cm[mb][j][i] = 0.0f; cl[mb][j][i] = 0.0f; }

    auto load_stage = [&](int kt, int st) {
        const int koff = kt << 5;
        const uint32_t base = sb + st * STAGE_B;
#pragma unroll
        for (int p = 0; p < 4; p++) {
            cpasync16(base + p * PLANE_B + r0c * (SROW * 2) + kp0 * 16,
                      gp[p] + (size_t)r0c * K + koff + kp0 * 8);
            cpasync16(base + p * PLANE_B + r1c * (SROW * 2) + kp1 * 16,
                      gp[p] + (size_t)r1c * K + koff + kp1 * 8);
        }
        CP_COMMIT();
    };

    load_stage(0, 0);
    load_stage(1, 1);

    for (int kt = 0; kt < nk; kt++) {
        if (kt + 1 < nk) asm volatile("cp.async.wait_group 1;" ::: "memory");
        else             asm volatile("cp.async.wait_group 0;" ::: "memory");
        __syncthreads();
        if (kt + 2 < nk) load_stage(kt + 2, (kt + 2) % NSTAGE);

        const int st = kt % NSTAGE;
        const __half* sAhi = smh + st * STAGE_H;
        const __half* sAlo = sAhi + PLANE_H;
        const __half* sBhi = sAlo + PLANE_H;
        const __half* sBlo = sBhi + PLANE_H;

#pragma unroll
        for (int ks = 0; ks < 2; ks++) {
            const int kb = ks * 16 + 2 * tig;
            uint32_t ah[2][4], al[2][4];
#pragma unroll
            for (int mb = 0; mb < 2; mb++) {
                const int r = mo + mb * 16 + grp;
                ah[mb][0] = *(const uint32_t*)(sAhi + r * SROW + kb);
                ah[mb][1] = *(const uint32_t*)(sAhi + (r + 8) * SROW + kb);
                ah[mb][2] = *(const uint32_t*)(sAhi + r * SROW + kb + 8);
                ah[mb][3] = *(const uint32_t*)(sAhi + (r + 8) * SROW + kb + 8);
                al[mb][0] = *(const uint32_t*)(sAlo + r * SROW + kb);
                al[mb][1] = *(const uint32_t*)(sAlo + (r + 8) * SROW + kb);
                al[mb][2] = *(const uint32_t*)(sAlo + r * SROW + kb + 8);
                al[mb][3] = *(const uint32_t*)(sAlo + (r + 8) * SROW + kb + 8);
            }
#pragma unroll
            for (int j = 0; j < 8; j++) {
                const int n = no + j * 8 + grp;
                uint32_t bh[2], bl[2];
                bh[0] = *(const uint32_t*)(sBhi + n * SROW + kb);
                bh[1] = *(const uint32_t*)(sBhi + n * SROW + kb + 8);
                bl[0] = *(const uint32_t*)(sBlo + n * SROW + kb);
                bl[1] = *(const uint32_t*)(sBlo + n * SROW + kb + 8);
#pragma unroll
                for (int mb = 0; mb < 2; mb++) {
                    mma16(cm[mb][j], ah[mb], bh);
                    mma16(cl[mb][j], ah[mb], bl);
                    mma16(cl[mb][j], al[mb], bh);
                }
            }
        }
        __syncthreads();
    }

    // epilogue: C = cm + cl*2^-11   (bias added by consumers)
#pragma unroll
    for (int mb = 0; mb < 2; mb++) {
#pragma unroll
        for (int j = 0; j < 8; j++) {
            const int col = n0 + no + j * 8 + 2 * tig;
            const int r0 = m0 + mo + mb * 16 + grp;
            const int r1 = r0 + 8;
            float2 v0, v1;
            v0.x = cm[mb][j][0] + cl[mb][j][0] * LO_INV;
            v0.y = cm[mb][j][1] + cl[mb][j][1] * LO_INV;
            v1.x = cm[mb][j][2] + cl[mb][j][2] * LO_INV;
            v1.y = cm[mb][j][3] + cl[mb][j][3] * LO_INV;
            *(float2*)(C + (size_t)r0 * N + col) = v0;
            *(float2*)(C + (size_t)r1 * N + col) = v1;
        }
    }
}

// ======================= small kernels ======================================
__device__ __forceinline__ void split_h(float a, __half* hi, __half* lo) {
    __half h = __float2half_rn(a);
    float r = a - __half2float(h);
    *hi = h;
    *lo = __float2half_rn(r * LO_SCALE);
}

__global__ void k_split(const float* __restrict__ src, __half* __restrict__ hi,
                        __half* __restrict__ lo, int n)
{
    int i = blockIdx.x * blockDim.x + threadIdx.x;
    if (i < n) split_h(src[i], hi + i, lo + i);
}

__global__ void k_init(const float* __restrict__ x, float* __restrict__ out)
{
    int i = blockIdx.x * blockDim.x + threadIdx.x;
    float L = logf(expf(1.0f) + (float)(VV - 1));
    if (i < BB * VV) {
        int b = i / VV, v = i % VV;
        out[(size_t)b * TT * VV + v] = (v == 0 ? 1.0f : 0.0f) - L;
    }
    if (i < BB * HH) {
        float h = x[i];
        g_h[i] = h;
        split_h(h, g_h_hi + i, g_h_lo + i);
    }
    if (i < BB) g_idx[i] = 0;
}

// ======================= fused softmax + argmax + GRU gates ==================
// Block b: phase A (if doSoftmax): sum logits partials + cls_b, log_softmax ->
// out[b,t,:], argmax -> idx.  Phase B: GRU update of h[b,:] using that idx,
// gh partial sums + b_hh, eproj gather + b_ih; re-split h to fp16 hi/lo.
__global__ __launch_bounds__(1024)
void k_post(float* __restrict__ out, int t, int doSoftmax,
            const float* __restrict__ cls_b,
            const float* __restrict__ b_ih,
            const float* __restrict__ b_hh)
{
    const int b = blockIdx.x;
    const int tid = threadIdx.x;

    __shared__ float s_v[1024];
    __shared__ int   s_i[1024];

    int gidx;
    if (doSoftmax) {
        const float* lp = g_logits_p + (size_t)b * VV;
        float* orow = out + ((size_t)b * TT + t) * VV;

        float x[8];
        float mx = -__int_as_float(0x7f800000);
        int   ai = 0;
#pragma unroll
        for (int j = 0; j < 8; j++) {
            int idx = tid + j * 1024;
            x[j] = lp[idx] + lp[idx + LSTRIDE] + lp[idx + 2 * LSTRIDE] + cls_b[idx];
            if (x[j] > mx) { mx = x[j]; ai = idx; }
        }
        s_v[tid] = mx; s_i[tid] = ai;
        __syncthreads();
#pragma unroll
        for (int s = 512; s > 0; s >>= 1) {
            if (tid < s) {
                float v2 = s_v[tid + s]; int i2 = s_i[tid + s];
                if (v2 > s_v[tid] || (v2 == s_v[tid] && i2 < s_i[tid])) {
                    s_v[tid] = v2; s_i[tid] = i2;
                }
            }
            __syncthreads();
        }
        float gmax = s_v[0];
        gidx = s_i[0];
        __syncthreads();

        float sum = 0.0f;
#pragma unroll
        for (int j = 0; j < 8; j++) sum += expf(x[j] - gmax);
        s_v[tid] = sum;
        __syncthreads();
#pragma unroll
        for (int s = 512; s > 0; s >>= 1) {
            if (tid < s) s_v[tid] += s_v[tid + s];
            __syncthreads();
        }
        float lse = gmax + logf(s_v[0]);

#pragma unroll
        for (int j = 0; j < 8; j++)
            orow[tid + j * 1024] = x[j] - lse;

        if (tid == 0) g_idx[b] = gidx;
    } else {
        gidx = g_idx[b];
    }

    // ---- phase B: GRU gates for h[b, tid] ----
    {
        const int i = tid;                 // 0..1023
        const int g = b * HH + i;
        const float* ep = g_eproj + (size_t)gidx * H3;
        const float* gp = g_gh_p + (size_t)b * H3;

        float gi_r = ep[i]           + b_ih[i];
        float gi_z = ep[HH + i]      + b_ih[HH + i];
        float gi_n = ep[2 * HH + i]  + b_ih[2 * HH + i];

        float gh_r = gp[i] + gp[i + GSTRIDE] + gp[i + 2 * GSTRIDE] + b_hh[i];
        float gh_z = gp[HH + i] + gp[HH + i + GSTRIDE] + gp[HH + i + 2 * GSTRIDE]
                   + b_hh[HH + i];
        float gh_n = gp[2 * HH + i] + gp[2 * HH + i + GSTRIDE]
                   + gp[2 * HH + i + 2 * GSTRIDE] + b_hh[2 * HH + i];

        float r = 1.0f / (1.0f + expf(-(gi_r + gh_r)));
        float z = 1.0f / (1.0f + expf(-(gi_z + gh_z)));
        float n = tanhf(gi_n + r * gh_n);
        float hn = (1.0f - z) * n + z * g_h[g];
        g_h[g] = hn;
        split_h(hn, g_h_hi + g, g_h_lo + g);
    }
}

// ======================= launch =============================================
extern "C" void kernel_launch(void* const* d_in, const int* in_sizes, int n_in,
                              void* d_out, int out_size)
{
    const float* x     = (const float*)d_in[0];
    const float* emb   = (const float*)d_in[1];
    const float* w_ih  = (const float*)d_in[2];
    const float* w_hh  = (const float*)d_in[3];
    const float* b_ih  = (const float*)d_in[4];
    const float* b_hh  = (const float*)d_in[5];
    const float* cls_w = (const float*)d_in[6];
    const float* cls_b = (const float*)d_in[7];
    float* out = (float*)d_out;

    float *eproj, *gh_p, *logits_p;
    __half *h_hi, *h_lo, *emb_hi, *emb_lo, *wih_hi, *wih_lo,
           *whh_hi, *whh_lo, *cls_hi, *cls_lo;
    cudaGetSymbolAddress((void**)&eproj,    g_eproj);
    cudaGetSymbolAddress((void**)&gh_p,     g_gh_p);
    cudaGetSymbolAddress((void**)&logits_p, g_logits_p);
    cudaGetSymbolAddress((void**)&h_hi,   g_h_hi);
    cudaGetSymbolAddress((void**)&h_lo,   g_h_lo);
    cudaGetSymbolAddress((void**)&emb_hi, g_emb_hi);
    cudaGetSymbolAddress((void**)&emb_lo, g_emb_lo);
    cudaGetSymbolAddress((void**)&wih_hi, g_wih_hi);
    cudaGetSymbolAddress((void**)&wih_lo, g_wih_lo);
    cudaGetSymbolAddress((void**)&whh_hi, g_whh_hi);
    cudaGetSymbolAddress((void**)&whh_lo, g_whh_lo);
    cudaGetSymbolAddress((void**)&cls_hi, g_cls_hi);
    cudaGetSymbolAddress((void**)&cls_lo, g_cls_lo);

    cudaFuncSetAttribute(k_gemm_h, cudaFuncAttributeMaxDynamicSharedMemorySize,
                         GEMM_SMEM_B);

    k_init<<<(BB * VV + 255) / 256, 256>>>(x, out);

    k_split<<<(VV * EMB + 255) / 256, 256>>>(emb,   emb_hi, emb_lo, VV * EMB);
    k_split<<<(H3 * EMB + 255) / 256, 256>>>(w_ih,  wih_hi, wih_lo, H3 * EMB);
    k_split<<<(H3 * HH  + 255) / 256, 256>>>(w_hh,  whh_hi, whh_lo, H3 * HH);
    k_split<<<(VV * HH  + 255) / 256, 256>>>(cls_w, cls_hi, cls_lo, VV * HH);

    // E_proj = emb @ w_ih^T   [V, 3H]  (no split-K; b_ih added in k_post)
    {
        const int nT = (VV / 128) * (H3 / 128);     // 1536
        k_gemm_h<<<nT, 256, GEMM_SMEM_B>>>(
            emb_hi, emb_lo,
            wih_hi, wih_lo, eproj, H3, nT, 0,
            wih_hi, wih_lo, eproj, H3, 0,
            EMB, nT, EMB / 32);
    }

    const int nGh  = H3 / 128;      // 24
    const int nCls = VV / 128;      // 64
    const int nT   = nGh + nCls;    // 88
    const int ktPer = 11;           // ceil(32/3): splits 11/11/10

    // gh(1) partials = h0 @ w_hh^T   (gh-only, split-K x3: grid 72)
    k_gemm_h<<<nGh * NSPLIT, 256, GEMM_SMEM_B>>>(
        h_hi, h_lo,
        whh_hi, whh_lo, gh_p, H3, nGh, GSTRIDE,
        whh_hi, whh_lo, gh_p, H3, GSTRIDE,
        HH, nGh, ktPer);

    // gates only: h(1) from idx0=0, gh(1)
    k_post<<<BB, 1024>>>(out, 0, 0, cls_b, b_ih, b_hh);

    for (int t = 1; t < TT; t++) {
        // fused split-K GEMM: gh(t+1) partials + logits(t) partials  (grid 264)
        k_gemm_h<<<nT * NSPLIT, 256, GEMM_SMEM_B>>>(
            h_hi, h_lo,
            whh_hi, whh_lo, gh_p, H3, nGh, GSTRIDE,
            cls_hi, cls_lo, logits_p, VV, LSTRIDE,
            HH, nT, ktPer);
        // softmax(t) + argmax + gates -> h(t+1)
        k_post<<<BB, 1024>>>(out, t, 1, cls_b, b_ih, b_hh);
    }
}

// round 7
// speedup vs baseline: 3.2901x; 1.0505x over previous
#include <cuda_runtime.h>
#include <cuda_fp16.h>
#include <math.h>
#include <stdint.h>

#define BB  128
#define EMB 512
#define HH  1024
#define H3  3072
#define VV  8192
#define TT  100

#define LO_SCALE   2048.0f
#define LO_INV     (1.0f / 2048.0f)

#define NSPLIT  3
#define LSTRIDE (BB * VV)
#define GSTRIDE (BB * H3)

// ======================= device scratch (no allocs allowed) ==================
__device__ float g_h[BB * HH];
__device__ int   g_idx[BB];
__device__ float g_eproj[(size_t)VV * H3];
__device__ float g_gh_p[NSPLIT * BB * H3];
__device__ float g_logits_p[NSPLIT * BB * VV];

__device__ __align__(128) __half g_h_hi[BB * HH];
__device__ __align__(128) __half g_h_lo[BB * HH];
__device__ __align__(128) __half g_emb_hi[(size_t)VV * EMB];
__device__ __align__(128) __half g_emb_lo[(size_t)VV * EMB];
__device__ __align__(128) __half g_wih_hi[(size_t)H3 * EMB];
__device__ __align__(128) __half g_wih_lo[(size_t)H3 * EMB];
__device__ __align__(128) __half g_whh_hi[(size_t)H3 * HH];
__device__ __align__(128) __half g_whh_lo[(size_t)H3 * HH];
__device__ __align__(128) __half g_cls_hi[(size_t)VV * HH];
__device__ __align__(128) __half g_cls_lo[(size_t)VV * HH];

// ======================= helpers ============================================
__device__ __forceinline__ uint32_t smem_u32(const void* p) {
    uint32_t a;
    asm("{ .reg .u64 t; cvta.to.shared.u64 t, %1; cvt.u32.u64 %0, t; }"
        : "=r"(a) : "l"(p));
    return a;
}
__device__ __forceinline__ void cpasync16(uint32_t dst, const void* src) {
    asm volatile("cp.async.cg.shared.global [%0], [%1], 16;"
                 :: "r"(dst), "l"(src) : "memory");
}
#define CP_COMMIT() asm volatile("cp.async.commit_group;" ::: "memory")

__device__ __forceinline__ void mma16(float c[4], const uint32_t a[4], const uint32_t b[2]) {
    asm volatile(
        "mma.sync.aligned.m16n8k16.row.col.f32.f16.f16.f32 "
        "{%0,%1,%2,%3}, {%4,%5,%6,%7}, {%8,%9}, {%0,%1,%2,%3};"
        : "+f"(c[0]), "+f"(c[1]), "+f"(c[2]), "+f"(c[3])
        : "r"(a[0]), "r"(a[1]), "r"(a[2]), "r"(a[3]), "r"(b[0]), "r"(b[1]));
}

#define LDSM_X4(r0, r1, r2, r3, addr) \
    asm volatile("ldmatrix.sync.aligned.m8n8.x4.shared.b16 {%0,%1,%2,%3}, [%4];" \
                 : "=r"(r0), "=r"(r1), "=r"(r2), "=r"(r3) : "r"(addr))

// ======================= fp16 split-precision GEMM (split-K) =================
// C_s[M,N] = (Ahi + Alo*2^-11)[M,Ks] @ (Bhi + Blo*2^-11)[N,Ks]^T  (no bias)
// CTA tile 128x128, BK=32, 256 threads, 4-stage cp.async, ldmatrix fragments.
#define SROW        40                    // halfs per smem row (80B pitch)
#define PLANE_H     (128 * SROW)
#define PLANE_B     (PLANE_H * 2)
#define STAGE_H     (4 * PLANE_H)
#define STAGE_B     (4 * PLANE_B)         // 40960
#define NSTAGE      4
#define GEMM_SMEM_B (NSTAGE * STAGE_B)    // 163840

__global__ __launch_bounds__(256, 1)
void k_gemm_h(const __half* __restrict__ Ahi, const __half* __restrict__ Alo,
              const __half* __restrict__ B1hi, const __half* __restrict__ B1lo,
              float* __restrict__ C1, int N1, int nT1, int stride1,
              const __half* __restrict__ B2hi, const __half* __restrict__ B2lo,
              float* __restrict__ C2, int N2, int stride2,
              int K, int nTiles, int ktPer)
{
    extern __shared__ __half smh[];
    const uint32_t sb = smem_u32(smh);

    const int tid  = threadIdx.x;
    const int wid  = tid >> 5, lane = tid & 31;
    const int grp  = lane >> 2, tig = lane & 3;
    const int wm   = wid & 3, wn = wid >> 2;
    const int mo   = wm * 32, no = wn * 64;

    // decode split + tile
    const int sK = blockIdx.x / nTiles;
    int id = blockIdx.x % nTiles;
    const __half *Bhi, *Blo; float* C; int N;
    if (id < nT1) { Bhi = B1hi; Blo = B1lo; C = C1 + (size_t)sK * stride1; N = N1; }
    else { id -= nT1; Bhi = B2hi; Blo = B2lo; C = C2 + (size_t)sK * stride2; N = N2; }
    const int ntn = N >> 7;
    const int tn = id % ntn, tm = id / ntn;
    const int m0 = tm << 7, n0 = tn << 7;

    const int nkAll = K >> 5;
    const int kt0 = sK * ktPer;
    const int nk = min(ktPer, nkAll - kt0);

    const __half* gp[4];
    gp[0] = Ahi + (size_t)m0 * K + (kt0 << 5);
    gp[1] = Alo + (size_t)m0 * K + (kt0 << 5);
    gp[2] = Bhi + (size_t)n0 * K + (kt0 << 5);
    gp[3] = Blo + (size_t)n0 * K + (kt0 << 5);

    const int r0c = tid >> 2,         kp0 = tid & 3;
    const int r1c = (tid + 256) >> 2, kp1 = (tid + 256) & 3;

    // ldmatrix per-lane address constants (byte offsets within a plane)
    // A: quads = {rows+0 k0, rows+8 k0, rows+0 k8, rows+8 k8}
    const uint32_t offA = (uint32_t)((mo + (lane & 7) + ((lane >> 3) & 1) * 8) * SROW
                                     + (lane >> 4) * 8) * 2;
    // B: quads = {nblk jj k0, nblk jj k8, nblk jj+1 k0, nblk jj+1 k8}
    const uint32_t offB = (uint32_t)((no + (lane & 7) + (lane >> 4) * 8) * SROW
                                     + ((lane >> 3) & 1) * 8) * 2;

    float cm[2][8][4], cl[2][8][4];
#pragma unroll
    for (int mb = 0; mb < 2; mb++)
#pragma unroll
        for (int j = 0; j < 8; j++)
#pragma unroll
            for (int i = 0; i < 4; i++) { cm[mb][j][i] = 0.0f; cl[mb][j][i] = 0.0f; }

    auto load_stage = [&](int kt, int st) {
        const int koff = kt << 5;
        const uint32_t base = sb + st * STAGE_B;
#pragma unroll
        for (int p = 0; p < 4; p++) {
            cpasync16(base + p * PLANE_B + r0c * (SROW * 2) + kp0 * 16,
                      gp[p] + (size_t)r0c * K + koff + kp0 * 8);
            cpasync16(base + p * PLANE_B + r1c * (SROW * 2) + kp1 * 16,
                      gp[p] + (size_t)r1c * K + koff + kp1 * 8);
        }
        CP_COMMIT();
    };

    load_stage(0, 0);
    if (nk > 1) load_stage(1, 1);

    for (int kt = 0; kt < nk; kt++) {
        if (kt + 1 < nk) asm volatile("cp.async.wait_group 1;" ::: "memory");
        else             asm volatile("cp.async.wait_group 0;" ::: "memory");
        __syncthreads();
        if (kt + 2 < nk) load_stage(kt + 2, (kt + 2) & (NSTAGE - 1));

        const uint32_t stb = sb + (kt & (NSTAGE - 1)) * STAGE_B;
        const uint32_t aHi = stb + offA;
        const uint32_t aLo = aHi + PLANE_B;
        const uint32_t bHi = stb + 2 * PLANE_B + offB;
        const uint32_t bLo = bHi + PLANE_B;

#pragma unroll
        for (int ks = 0; ks < 2; ks++) {
            const uint32_t kso = ks * 32;
            uint32_t ah[2][4], al[2][4];
#pragma unroll
            for (int mb = 0; mb < 2; mb++) {
                const uint32_t amb = mb * (16 * SROW * 2) + kso;
                LDSM_X4(ah[mb][0], ah[mb][1], ah[mb][2], ah[mb][3], aHi + amb);
                LDSM_X4(al[mb][0], al[mb][1], al[mb][2], al[mb][3], aLo + amb);
            }
#pragma unroll
            for (int jj = 0; jj < 8; jj += 2) {
                const uint32_t bj = jj * (8 * SROW * 2) + kso;
                uint32_t bh[2][2], bl[2][2];
                LDSM_X4(bh[0][0], bh[0][1], bh[1][0], bh[1][1], bHi + bj);
                LDSM_X4(bl[0][0], bl[0][1], bl[1][0], bl[1][1], bLo + bj);
#pragma unroll
                for (int q = 0; q < 2; q++) {
                    const int j = jj + q;
#pragma unroll
                    for (int mb = 0; mb < 2; mb++) {
                        mma16(cm[mb][j], ah[mb], bh[q]);
                        mma16(cl[mb][j], ah[mb], bl[q]);
                        mma16(cl[mb][j], al[mb], bh[q]);
                    }
                }
            }
        }
    }

    // epilogue: C = cm + cl*2^-11   (bias added by consumers)
#pragma unroll
    for (int mb = 0; mb < 2; mb++) {
#pragma unroll
        for (int j = 0; j < 8; j++) {
            const int col = n0 + no + j * 8 + 2 * tig;
            const int r0 = m0 + mo + mb * 16 + grp;
            const int r1 = r0 + 8;
            float2 v0, v1;
            v0.x = cm[mb][j][0] + cl[mb][j][0] * LO_INV;
            v0.y = cm[mb][j][1] + cl[mb][j][1] * LO_INV;
            v1.x = cm[mb][j][2] + cl[mb][j][2] * LO_INV;
            v1.y = cm[mb][j][3] + cl[mb][j][3] * LO_INV;
            *(float2*)(C + (size_t)r0 * N + col) = v0;
            *(float2*)(C + (size_t)r1 * N + col) = v1;
        }
    }
}

// ======================= small kernels ======================================
__device__ __forceinline__ void split_h(float a, __half* hi, __half* lo) {
    __half h = __float2half_rn(a);
    float r = a - __half2float(h);
    *hi = h;
    *lo = __float2half_rn(r * LO_SCALE);
}

__global__ void k_split(const float* __restrict__ src, __half* __restrict__ hi,
                        __half* __restrict__ lo, int n)
{
    int i = blockIdx.x * blockDim.x + threadIdx.x;
    if (i < n) split_h(src[i], hi + i, lo + i);
}

__global__ void k_init(const float* __restrict__ x, float* __restrict__ out)
{
    int i = blockIdx.x * blockDim.x + threadIdx.x;
    float L = logf(expf(1.0f) + (float)(VV - 1));
    if (i < BB * VV) {
        int b = i / VV, v = i % VV;
        out[(size_t)b * TT * VV + v] = (v == 0 ? 1.0f : 0.0f) - L;
    }
    if (i < BB * HH) {
        float h = x[i];
        g_h[i] = h;
        split_h(h, g_h_hi + i, g_h_lo + i);
    }
    if (i < BB) g_idx[i] = 0;
}

// ======================= fused softmax + argmax + GRU gates ==================
__global__ __launch_bounds__(1024)
void k_post(float* __restrict__ out, int t, int doSoftmax,
            const float* __restrict__ cls_b,
            const float* __restrict__ b_ih,
            const float* __restrict__ b_hh)
{
    const int b = blockIdx.x;
    const int tid = threadIdx.x;

    __shared__ float s_v[1024];
    __shared__ int   s_i[1024];

    int gidx;
    if (doSoftmax) {
        const float* lp = g_logits_p + (size_t)b * VV;
        float* orow = out + ((size_t)b * TT + t) * VV;

        float x[8];
        float mx = -__int_as_float(0x7f800000);
        int   ai = 0;
#pragma unroll
        for (int j = 0; j < 8; j++) {
            int idx = tid + j * 1024;
            x[j] = lp[idx] + lp[idx + LSTRIDE] + lp[idx + 2 * LSTRIDE] + cls_b[idx];
            if (x[j] > mx) { mx = x[j]; ai = idx; }
        }
        s_v[tid] = mx; s_i[tid] = ai;
        __syncthreads();
#pragma unroll
        for (int s = 512; s > 0; s >>= 1) {
            if (tid < s) {
                float v2 = s_v[tid + s]; int i2 = s_i[tid + s];
                if (v2 > s_v[tid] || (v2 == s_v[tid] && i2 < s_i[tid])) {
                    s_v[tid] = v2; s_i[tid] = i2;
                }
            }
            __syncthreads();
        }
        float gmax = s_v[0];
        gidx = s_i[0];
        __syncthreads();

        float sum = 0.0f;
#pragma unroll
        for (int j = 0; j < 8; j++) sum += __expf(x[j] - gmax);
        s_v[tid] = sum;
        __syncthreads();
#pragma unroll
        for (int s = 512; s > 0; s >>= 1) {
            if (tid < s) s_v[tid] += s_v[tid + s];
            __syncthreads();
        }
        float lse = gmax + logf(s_v[0]);

#pragma unroll
        for (int j = 0; j < 8; j++)
            orow[tid + j * 1024] = x[j] - lse;

        if (tid == 0) g_idx[b] = gidx;
    } else {
        gidx = g_idx[b];
    }

    // ---- GRU gates for h[b, tid] ----
    {
        const int i = tid;
        const int g = b * HH + i;
        const float* ep = g_eproj + (size_t)gidx * H3;
        const float* gp = g_gh_p + (size_t)b * H3;

        float gi_r = ep[i]          + b_ih[i];
        float gi_z = ep[HH + i]     + b_ih[HH + i];
        float gi_n = ep[2 * HH + i] + b_ih[2 * HH + i];

        float gh_r = gp[i] + gp[i + GSTRIDE] + gp[i + 2 * GSTRIDE] + b_hh[i];
        float gh_z = gp[HH + i] + gp[HH + i + GSTRIDE] + gp[HH + i + 2 * GSTRIDE]
                   + b_hh[HH + i];
        float gh_n = gp[2 * HH + i] + gp[2 * HH + i + GSTRIDE]
                   + gp[2 * HH + i + 2 * GSTRIDE] + b_hh[2 * HH + i];

        float r = 1.0f / (1.0f + expf(-(gi_r + gh_r)));
        float z = 1.0f / (1.0f + expf(-(gi_z + gh_z)));
        float n = tanhf(gi_n + r * gh_n);
        float hn = (1.0f - z) * n + z * g_h[g];
        g_h[g] = hn;
        split_h(hn, g_h_hi + g, g_h_lo + g);
    }
}

// ======================= launch =============================================
extern "C" void kernel_launch(void* const* d_in, const int* in_sizes, int n_in,
                              void* d_out, int out_size)
{
    const float* x     = (const float*)d_in[0];
    const float* emb   = (const float*)d_in[1];
    const float* w_ih  = (const float*)d_in[2];
    const float* w_hh  = (const float*)d_in[3];
    const float* b_ih  = (const float*)d_in[4];
    const float* b_hh  = (const float*)d_in[5];
    const float* cls_w = (const float*)d_in[6];
    const float* cls_b = (const float*)d_in[7];
    float* out = (float*)d_out;

    float *eproj, *gh_p, *logits_p;
    __half *h_hi, *h_lo, *emb_hi, *emb_lo, *wih_hi, *wih_lo,
           *whh_hi, *whh_lo, *cls_hi, *cls_lo;
    cudaGetSymbolAddress((void**)&eproj,    g_eproj);
    cudaGetSymbolAddress((void**)&gh_p,     g_gh_p);
    cudaGetSymbolAddress((void**)&logits_p, g_logits_p);
    cudaGetSymbolAddress((void**)&h_hi,   g_h_hi);
    cudaGetSymbolAddress((void**)&h_lo,   g_h_lo);
    cudaGetSymbolAddress((void**)&emb_hi, g_emb_hi);
    cudaGetSymbolAddress((void**)&emb_lo, g_emb_lo);
    cudaGetSymbolAddress((void**)&wih_hi, g_wih_hi);
    cudaGetSymbolAddress((void**)&wih_lo, g_wih_lo);
    cudaGetSymbolAddress((void**)&whh_hi, g_whh_hi);
    cudaGetSymbolAddress((void**)&whh_lo, g_whh_lo);
    cudaGetSymbolAddress((void**)&cls_hi, g_cls_hi);
    cudaGetSymbolAddress((void**)&cls_lo, g_cls_lo);

    cudaFuncSetAttribute(k_gemm_h, cudaFuncAttributeMaxDynamicSharedMemorySize,
                         GEMM_SMEM_B);

    k_init<<<(BB * VV + 255) / 256, 256>>>(x, out);

    k_split<<<(VV * EMB + 255) / 256, 256>>>(emb,   emb_hi, emb_lo, VV * EMB);
    k_split<<<(H3 * EMB + 255) / 256, 256>>>(w_ih,  wih_hi, wih_lo, H3 * EMB);
    k_split<<<(H3 * HH  + 255) / 256, 256>>>(w_hh,  whh_hi, whh_lo, H3 * HH);
    k_split<<<(VV * HH  + 255) / 256, 256>>>(cls_w, cls_hi, cls_lo, VV * HH);

    // E_proj = emb @ w_ih^T   [V, 3H]  (no split-K; b_ih added in k_post)
    {
        const int nT = (VV / 128) * (H3 / 128);     // 1536
        k_gemm_h<<<nT, 256, GEMM_SMEM_B>>>(
            emb_hi, emb_lo,
            wih_hi, wih_lo, eproj, H3, nT, 0,
            wih_hi, wih_lo, eproj, H3, 0,
            EMB, nT, EMB / 32);
    }

    const int nGh  = H3 / 128;      // 24
    const int nCls = VV / 128;      // 64
    const int nT   = nGh + nCls;    // 88
    const int ktPer = 11;           // splits 11/11/10

    // gh(1) partials = h0 @ w_hh^T
    k_gemm_h<<<nGh * NSPLIT, 256, GEMM_SMEM_B>>>(
        h_hi, h_lo,
        whh_hi, whh_lo, gh_p, H3, nGh, GSTRIDE,
        whh_hi, whh_lo, gh_p, H3, GSTRIDE,
        HH, nGh, ktPer);

    // gates only: h(1) from idx0=0, gh(1)
    k_post<<<BB, 1024>>>(out, 0, 0, cls_b, b_ih, b_hh);

    for (int t = 1; t < TT; t++) {
        k_gemm_h<<<nT * NSPLIT, 256, GEMM_SMEM_B>>>(
            h_hi, h_lo,
            whh_hi, whh_lo, gh_p, H3, nGh, GSTRIDE,
            cls_hi, cls_lo, logits_p, VV, LSTRIDE,
            HH, nT, ktPer);
        k_post<<<BB, 1024>>>(out, t, 1, cls_b, b_ih, b_hh);
    }
}